// round 7
// baseline (speedup 1.0000x reference)
#include <cuda_runtime.h>
#include <math.h>

// ---------------- problem constants ----------------
#define BB     8
#define FF     8192
#define NL     64
#define DD     1024
#define HH     8
#define DHD    64
#define INNERD 512
#define KVLEN  (FF + NL)        // 8256
#define MROWS  (BB * KVLEN)     // 66048
#define NSPLIT 16
#define CHUNK  528              // 16*33; all split boundaries multiple of 16
#define QSCALE 0.125f           // 64^-0.5
#define NEGINF -1e30f

// ---------------- scratch (device globals; no allocs allowed) ----------------
__device__ float g_xn[BB * FF * DD];             // 256 MB  normalized x
__device__ float g_latn[BB * NL * DD];           // 2 MB    normalized latents (ungated)
__device__ float g_q[BB * NL * INNERD];          // q * SCALE
__device__ float g_k[MROWS * INNERD];            // 135 MB
__device__ float g_v[MROWS * INNERD];            // 135 MB
__device__ float g_sim[BB * HH * NL * KVLEN];    // 135 MB  sim -> attn (in place)
__device__ float g_opart[NSPLIT * BB * NL * INNERD]; // 16 MB split-K partials
__device__ float g_o[BB * NL * INNERD];          // attn @ v
__device__ int   g_mask_mode;                    // 0 = u8, 1 = i32, 2 = f32

// ---------------- mask dtype detection ----------------
// The harness has no bool dtype; the JAX bool mask arrives as u8, i32 or f32.
// Scan the first 64KB (valid under every hypothesis) and classify by which
// byte lanes (offset mod 4) ever hold nonzero bytes:
//   u8  0/1 : lane 1 hit (~50% of odd bytes are 1)        -> mode 0
//   f32 1.0f: bytes [00 00 80 3F], lanes 2/3 only          -> mode 2
//   i32 1   : bytes [01 00 00 00], lane 0 only             -> mode 1
// Deterministic per input; single block; graph-capturable.
__global__ void detect_mask_kernel(const unsigned int* __restrict__ mw) {
    __shared__ unsigned int sh[2];
    if (threadIdx.x == 0) { sh[0] = 0u; sh[1] = 0u; }
    __syncthreads();
    unsigned int a1 = 0u, a3 = 0u;
    for (int i = threadIdx.x; i < 16384; i += 256) {   // 16384 words = 64KB
        unsigned int w = mw[i];
        a1 |= (w & 0x0000FF00u);
        a3 |= (w & 0xFF000000u);
    }
#pragma unroll
    for (int o = 16; o; o >>= 1) {
        a1 |= __shfl_xor_sync(0xffffffffu, a1, o);
        a3 |= __shfl_xor_sync(0xffffffffu, a3, o);
    }
    if ((threadIdx.x & 31) == 0) { atomicOr(&sh[0], a1); atomicOr(&sh[1], a3); }
    __syncthreads();
    if (threadIdx.x == 0)
        g_mask_mode = sh[0] ? 0 : (sh[1] ? 2 : 1);
}

__device__ __forceinline__ int mask_padded(const void* mask, int mode, int idx) {
    if (mode == 0) return ((const unsigned char*)mask)[idx] != 0;
    if (mode == 1) return ((const int*)mask)[idx] != 0;
    return ((const float*)mask)[idx] != 0.0f;
}

// ---------------- LayerNorm: one row (1024) per block, 256 threads ----------------
__global__ void __launch_bounds__(256) ln_kernel(const float* __restrict__ in,
                                                 const float* __restrict__ gamma,
                                                 const float* __restrict__ beta,
                                                 float* __restrict__ out) {
    const int row = blockIdx.x;
    const int t = threadIdx.x;
    const float4* inr = reinterpret_cast<const float4*>(in + (size_t)row * DD);
    float4 v = inr[t];
    float s  = (v.x + v.y) + (v.z + v.w);
    float ss = v.x * v.x + v.y * v.y + v.z * v.z + v.w * v.w;

    __shared__ float red[16];
    __shared__ float s_mu, s_rstd;
#pragma unroll
    for (int o = 16; o; o >>= 1) {
        s  += __shfl_xor_sync(0xffffffffu, s, o);
        ss += __shfl_xor_sync(0xffffffffu, ss, o);
    }
    if ((t & 31) == 0) { red[t >> 5] = s; red[(t >> 5) + 8] = ss; }
    __syncthreads();
    if (t < 8) {
        float a = red[t], b2 = red[t + 8];
#pragma unroll
        for (int o = 4; o; o >>= 1) {
            a  += __shfl_xor_sync(0xffu, a, o);
            b2 += __shfl_xor_sync(0xffu, b2, o);
        }
        if (t == 0) {
            float mu  = a * (1.0f / DD);
            float var = b2 * (1.0f / DD) - mu * mu;
            s_mu = mu;
            s_rstd = rsqrtf(var + 1e-5f);
        }
    }
    __syncthreads();
    const float mu = s_mu, rstd = s_rstd;
    float4 g4 = reinterpret_cast<const float4*>(gamma)[t];
    float4 b4 = reinterpret_cast<const float4*>(beta)[t];
    float4 o4;
    o4.x = (v.x - mu) * rstd * g4.x + b4.x;
    o4.y = (v.y - mu) * rstd * g4.y + b4.y;
    o4.z = (v.z - mu) * rstd * g4.z + b4.z;
    o4.w = (v.w - mu) * rstd * g4.w + b4.w;
    reinterpret_cast<float4*>(out + (size_t)row * DD)[t] = o4;
}

// ---------------- fused K/V GEMM: [66048 x 1024] @ (Wk|Wv)[1024 x 512] ----------------
__global__ void __launch_bounds__(256) kv_gemm_kernel(const float* __restrict__ Wk,
                                                      const float* __restrict__ Wv,
                                                      const float* __restrict__ gate_p) {
    __shared__ float As[16][132];
    __shared__ float Bks[16][64];
    __shared__ float Bvs[16][64];
    const int t  = threadIdx.x;
    const int n0 = blockIdx.x * 64;
    const int m0 = blockIdx.y * 128;
    const int tx = t & 15, ty = t >> 4;          // cols tx*4, rows ty*8
    const int arow = t >> 2, ak = (t & 3) * 4;   // A-tile loader coords
    const int brow = t >> 4, bc = (t & 15) * 4;  // B-tile loader coords
    const float gate = *gate_p;

    const float* aptr[2];
    float ascale[2];
#pragma unroll
    for (int i = 0; i < 2; i++) {
        int gr = m0 + arow + 64 * i;
        int b  = gr / KVLEN;
        int s  = gr - b * KVLEN;
        if (s < FF) { aptr[i] = g_xn   + (size_t)(b * FF + s)        * DD; ascale[i] = 1.0f; }
        else        { aptr[i] = g_latn + (size_t)(b * NL + (s - FF)) * DD; ascale[i] = gate; }
    }

    float acck[8][4], accv[8][4];
#pragma unroll
    for (int i = 0; i < 8; i++)
#pragma unroll
        for (int j = 0; j < 4; j++) { acck[i][j] = 0.f; accv[i][j] = 0.f; }

    for (int k0 = 0; k0 < DD; k0 += 16) {
#pragma unroll
        for (int i = 0; i < 2; i++) {
            float4 a4 = *reinterpret_cast<const float4*>(aptr[i] + k0 + ak);
            int r = arow + 64 * i;
            As[ak + 0][r] = a4.x * ascale[i];
            As[ak + 1][r] = a4.y * ascale[i];
            As[ak + 2][r] = a4.z * ascale[i];
            As[ak + 3][r] = a4.w * ascale[i];
        }
        *reinterpret_cast<float4*>(&Bks[brow][bc]) =
            *reinterpret_cast<const float4*>(Wk + (size_t)(k0 + brow) * INNERD + n0 + bc);
        *reinterpret_cast<float4*>(&Bvs[brow][bc]) =
            *reinterpret_cast<const float4*>(Wv + (size_t)(k0 + brow) * INNERD + n0 + bc);
        __syncthreads();
#pragma unroll
        for (int k = 0; k < 16; k++) {
            float af[8], bkf[4], bvf[4];
            *reinterpret_cast<float4*>(&af[0]) = *reinterpret_cast<const float4*>(&As[k][ty * 8]);
            *reinterpret_cast<float4*>(&af[4]) = *reinterpret_cast<const float4*>(&As[k][ty * 8 + 4]);
            *reinterpret_cast<float4*>(&bkf[0]) = *reinterpret_cast<const float4*>(&Bks[k][tx * 4]);
            *reinterpret_cast<float4*>(&bvf[0]) = *reinterpret_cast<const float4*>(&Bvs[k][tx * 4]);
#pragma unroll
            for (int i = 0; i < 8; i++)
#pragma unroll
                for (int j = 0; j < 4; j++) {
                    acck[i][j] += af[i] * bkf[j];
                    accv[i][j] += af[i] * bvf[j];
                }
        }
        __syncthreads();
    }
#pragma unroll
    for (int i = 0; i < 8; i++) {
        size_t gr = (size_t)(m0 + ty * 8 + i);
        *reinterpret_cast<float4*>(&g_k[gr * INNERD + n0 + tx * 4]) =
            make_float4(acck[i][0], acck[i][1], acck[i][2], acck[i][3]);
        *reinterpret_cast<float4*>(&g_v[gr * INNERD + n0 + tx * 4]) =
            make_float4(accv[i][0], accv[i][1], accv[i][2], accv[i][3]);
    }
}

// ---------------- generic small GEMM: C = alpha * A[MxK] @ B[KxN], 64x64 tiles ----------------
__global__ void __launch_bounds__(256) gemm64_kernel(const float* __restrict__ A,
                                                     const float* __restrict__ Bm,
                                                     float* __restrict__ C,
                                                     int M, int N, int K, float alpha) {
    __shared__ float As[16][68];
    __shared__ float Bs[16][64];
    const int t  = threadIdx.x;
    const int m0 = blockIdx.y * 64, n0 = blockIdx.x * 64;
    const int tx = t & 15, ty = t >> 4;
    const int arow = t >> 2, ak = (t & 3) * 4;
    const int brow = t >> 4, bc = (t & 15) * 4;
    float acc[4][4];
#pragma unroll
    for (int i = 0; i < 4; i++)
#pragma unroll
        for (int j = 0; j < 4; j++) acc[i][j] = 0.f;

    for (int k0 = 0; k0 < K; k0 += 16) {
        float4 a4 = *reinterpret_cast<const float4*>(A + (size_t)(m0 + arow) * K + k0 + ak);
        As[ak + 0][arow] = a4.x;
        As[ak + 1][arow] = a4.y;
        As[ak + 2][arow] = a4.z;
        As[ak + 3][arow] = a4.w;
        *reinterpret_cast<float4*>(&Bs[brow][bc]) =
            *reinterpret_cast<const float4*>(Bm + (size_t)(k0 + brow) * N + n0 + bc);
        __syncthreads();
#pragma unroll
        for (int k = 0; k < 16; k++) {
            float af[4], bf[4];
            *reinterpret_cast<float4*>(&af[0]) = *reinterpret_cast<const float4*>(&As[k][ty * 4]);
            *reinterpret_cast<float4*>(&bf[0]) = *reinterpret_cast<const float4*>(&Bs[k][tx * 4]);
#pragma unroll
            for (int i = 0; i < 4; i++)
#pragma unroll
                for (int j = 0; j < 4; j++) acc[i][j] += af[i] * bf[j];
        }
        __syncthreads();
    }
#pragma unroll
    for (int i = 0; i < 4; i++)
        *reinterpret_cast<float4*>(&C[(size_t)(m0 + ty * 4 + i) * N + n0 + tx * 4]) =
            make_float4(acc[i][0] * alpha, acc[i][1] * alpha, acc[i][2] * alpha, acc[i][3] * alpha);
}

// ---------------- sim = (q*SCALE) @ k^T per (b,h), fused padding mask ----------------
__global__ void __launch_bounds__(256) sim_kernel(const void* __restrict__ mask) {
    __shared__ float Qs[16][64];
    __shared__ float Ks[16][132];
    const int t   = threadIdx.x;
    const int bh  = blockIdx.y;
    const int b   = bh >> 3, h = bh & 7;
    const int kv0 = blockIdx.x * 128;
    const int tx = t & 15, ty = t >> 4;          // kv group tx*8, q group ty*4
    const int lrow = t >> 2, ld = (t & 3) * 4;   // loader coords

    float acc[4][8];
#pragma unroll
    for (int i = 0; i < 4; i++)
#pragma unroll
        for (int j = 0; j < 8; j++) acc[i][j] = 0.f;

    const float* qbase = g_q + (size_t)b * NL * INNERD + h * DHD;
    const float* kbase = g_k + (size_t)b * KVLEN * INNERD + h * DHD;

    for (int d0 = 0; d0 < DHD; d0 += 16) {
        float4 q4 = *reinterpret_cast<const float4*>(qbase + (size_t)lrow * INNERD + d0 + ld);
        Qs[ld + 0][lrow] = q4.x;
        Qs[ld + 1][lrow] = q4.y;
        Qs[ld + 2][lrow] = q4.z;
        Qs[ld + 3][lrow] = q4.w;
#pragma unroll
        for (int i = 0; i < 2; i++) {
            int kr = kv0 + lrow + 64 * i;
            float4 k4 = make_float4(0.f, 0.f, 0.f, 0.f);
            if (kr < KVLEN)
                k4 = *reinterpret_cast<const float4*>(kbase + (size_t)kr * INNERD + d0 + ld);
            Ks[ld + 0][lrow + 64 * i] = k4.x;
            Ks[ld + 1][lrow + 64 * i] = k4.y;
            Ks[ld + 2][lrow + 64 * i] = k4.z;
            Ks[ld + 3][lrow + 64 * i] = k4.w;
        }
        __syncthreads();
#pragma unroll
        for (int k = 0; k < 16; k++) {
            float qf[4], kf[8];
            *reinterpret_cast<float4*>(&qf[0]) = *reinterpret_cast<const float4*>(&Qs[k][ty * 4]);
            *reinterpret_cast<float4*>(&kf[0]) = *reinterpret_cast<const float4*>(&Ks[k][tx * 8]);
            *reinterpret_cast<float4*>(&kf[4]) = *reinterpret_cast<const float4*>(&Ks[k][tx * 8 + 4]);
#pragma unroll
            for (int i = 0; i < 4; i++)
#pragma unroll
                for (int j = 0; j < 8; j++) acc[i][j] += qf[i] * kf[j];
        }
        __syncthreads();
    }

    const int kvb = kv0 + tx * 8;
    if (kvb < KVLEN) {                       // KVLEN % 8 == 0: groups all-in or all-out
        const int mode = g_mask_mode;
        int inval[8];
#pragma unroll
        for (int j = 0; j < 8; j++) {
            int kv = kvb + j;
            inval[j] = (kv < FF) && mask_padded(mask, mode, b * FF + kv); // True = padded
        }
#pragma unroll
        for (int i = 0; i < 4; i++) {
            int q = ty * 4 + i;
            float* dst = g_sim + ((size_t)bh * NL + q) * KVLEN + kvb;
            float o[8];
#pragma unroll
            for (int j = 0; j < 8; j++) o[j] = inval[j] ? NEGINF : acc[i][j];
            *reinterpret_cast<float4*>(&dst[0]) = *reinterpret_cast<float4*>(&o[0]);
            *reinterpret_cast<float4*>(&dst[4]) = *reinterpret_cast<float4*>(&o[4]);
        }
    }
}

// ---------------- softmax over rows of g_sim (4096 rows x 8256), in place ----------------
__global__ void __launch_bounds__(256) softmax_kernel() {
    const int row = blockIdx.x;
    const int t = threadIdx.x;
    float* p = g_sim + (size_t)row * KVLEN;
    const int NV = KVLEN / 4;   // 2064 float4
    float4 v[9];
    float m = -3.4e38f;
#pragma unroll
    for (int i = 0; i < 9; i++) {
        int idx = t + 256 * i;
        if (idx < NV) {
            v[i] = *(reinterpret_cast<const float4*>(p) + idx);
            m = fmaxf(m, fmaxf(fmaxf(v[i].x, v[i].y), fmaxf(v[i].z, v[i].w)));
        }
    }
    __shared__ float red[8];
    __shared__ float s_max, s_sum;
#pragma unroll
    for (int o = 16; o; o >>= 1) m = fmaxf(m, __shfl_xor_sync(0xffffffffu, m, o));
    if ((t & 31) == 0) red[t >> 5] = m;
    __syncthreads();
    if (t < 8) {
        float a = red[t];
#pragma unroll
        for (int o = 4; o; o >>= 1) a = fmaxf(a, __shfl_xor_sync(0xffu, a, o));
        if (t == 0) s_max = a;
    }
    __syncthreads();
    m = s_max;
    float s = 0.f;
#pragma unroll
    for (int i = 0; i < 9; i++) {
        int idx = t + 256 * i;
        if (idx < NV) {
            v[i].x = __expf(v[i].x - m);   // masked (-1e30) underflows to exactly 0
            v[i].y = __expf(v[i].y - m);
            v[i].z = __expf(v[i].z - m);
            v[i].w = __expf(v[i].w - m);
            s += (v[i].x + v[i].y) + (v[i].z + v[i].w);
        }
    }
#pragma unroll
    for (int o = 16; o; o >>= 1) s += __shfl_xor_sync(0xffffffffu, s, o);
    __syncthreads();                      // protect red[] reuse
    if ((t & 31) == 0) red[t >> 5] = s;
    __syncthreads();
    if (t < 8) {
        float a = red[t];
#pragma unroll
        for (int o = 4; o; o >>= 1) a += __shfl_xor_sync(0xffu, a, o);
        if (t == 0) s_sum = a;
    }
    __syncthreads();
    const float r = 1.0f / s_sum;
#pragma unroll
    for (int i = 0; i < 9; i++) {
        int idx = t + 256 * i;
        if (idx < NV)
            *(reinterpret_cast<float4*>(p) + idx) =
                make_float4(v[i].x * r, v[i].y * r, v[i].z * r, v[i].w * r);
    }
}

// ---------------- attn @ v, split-K over kv into NSPLIT deterministic partials ----------------
__global__ void __launch_bounds__(256) pv_kernel() {
    const int split = blockIdx.x, bh = blockIdx.y;
    const int b = bh >> 3, h = bh & 7;
    const int kvs = split * CHUNK;
    const int kve = min(kvs + CHUNK, KVLEN);   // always multiple of 16 span
    __shared__ float Ps[16][68];
    __shared__ float Vs[16][68];
    const int t = threadIdx.x;
    const int tx = t & 15, ty = t >> 4;        // d group tx*4, q group ty*4
    const int prow = t >> 2, pk = (t & 3) * 4; // attn loader
    const int vrow = t >> 4, vd = (t & 15) * 4;// v loader
    float acc[4][4];
#pragma unroll
    for (int i = 0; i < 4; i++)
#pragma unroll
        for (int j = 0; j < 4; j++) acc[i][j] = 0.f;

    const float* pbase = g_sim + (size_t)bh * NL * KVLEN;
    const float* vbase = g_v + (size_t)b * KVLEN * INNERD + h * DHD;

    for (int k0 = kvs; k0 < kve; k0 += 16) {
        float4 a4 = *reinterpret_cast<const float4*>(pbase + (size_t)prow * KVLEN + k0 + pk);
        Ps[pk + 0][prow] = a4.x;
        Ps[pk + 1][prow] = a4.y;
        Ps[pk + 2][prow] = a4.z;
        Ps[pk + 3][prow] = a4.w;
        *reinterpret_cast<float4*>(&Vs[vrow][vd]) =
            *reinterpret_cast<const float4*>(vbase + (size_t)(k0 + vrow) * INNERD + vd);
        __syncthreads();
#pragma unroll
        for (int k = 0; k < 16; k++) {
            float pf[4], vf[4];
            *reinterpret_cast<float4*>(&pf[0]) = *reinterpret_cast<const float4*>(&Ps[k][ty * 4]);
            *reinterpret_cast<float4*>(&vf[0]) = *reinterpret_cast<const float4*>(&Vs[k][tx * 4]);
#pragma unroll
            for (int i = 0; i < 4; i++)
#pragma unroll
                for (int j = 0; j < 4; j++) acc[i][j] += pf[i] * vf[j];
        }
        __syncthreads();
    }

    float* obase = g_opart + (size_t)split * (BB * NL * INNERD)
                 + (size_t)(b * NL) * INNERD + h * DHD;
#pragma unroll
    for (int i = 0; i < 4; i++)
        *reinterpret_cast<float4*>(&obase[(size_t)(ty * 4 + i) * INNERD + tx * 4]) =
            make_float4(acc[i][0], acc[i][1], acc[i][2], acc[i][3]);
}

// ---------------- deterministic split-K reduction ----------------
__global__ void __launch_bounds__(256) reduce_kernel() {
    const int i = blockIdx.x * blockDim.x + threadIdx.x;
    float s = 0.f;
#pragma unroll
    for (int k = 0; k < NSPLIT; k++) s += g_opart[(size_t)k * (BB * NL * INNERD) + i];
    g_o[i] = s;
}

// ---------------- launch ----------------
extern "C" void kernel_launch(void* const* d_in, const int* in_sizes, int n_in,
                              void* d_out, int out_size) {
    const float* x    = (const float*)d_in[0];
    const float* lat  = (const float*)d_in[1];
    const void*  mask = d_in[2];                 // bool mask; dtype detected at runtime
    const float* gate = (const float*)d_in[3];
    const float* gm   = (const float*)d_in[4];
    const float* bm   = (const float*)d_in[5];
    const float* gl   = (const float*)d_in[6];
    const float* bl   = (const float*)d_in[7];
    const float* Wq   = (const float*)d_in[8];
    const float* Wk   = (const float*)d_in[9];
    const float* Wv   = (const float*)d_in[10];
    const float* Wout = (const float*)d_in[11];
    float* out = (float*)d_out;

    float *p_xn, *p_latn, *p_q, *p_o;
    cudaGetSymbolAddress((void**)&p_xn,   g_xn);
    cudaGetSymbolAddress((void**)&p_latn, g_latn);
    cudaGetSymbolAddress((void**)&p_q,    g_q);
    cudaGetSymbolAddress((void**)&p_o,    g_o);

    detect_mask_kernel<<<1, 256>>>((const unsigned int*)mask);
    ln_kernel<<<BB * FF, 256>>>(x, gm, bm, p_xn);
    ln_kernel<<<BB * NL, 256>>>(lat, gl, bl, p_latn);
    // q = LN(latents) @ Wq * SCALE   (M=512, N=512, K=1024)
    gemm64_kernel<<<dim3(INNERD / 64, (BB * NL) / 64), 256>>>(p_latn, Wq, p_q,
                                                              BB * NL, INNERD, DD, QSCALE);
    // k,v = [LN(x); LN(lat)*gate] @ {Wk,Wv}   (M=66048, N=512x2, K=1024) -- dominant
    kv_gemm_kernel<<<dim3(INNERD / 64, MROWS / 128), 256>>>(Wk, Wv, gate);
    // sim + mask
    sim_kernel<<<dim3((KVLEN + 127) / 128, BB * HH), 256>>>(mask);
    softmax_kernel<<<BB * HH * NL, 256>>>();
    pv_kernel<<<dim3(NSPLIT, BB * HH), 256>>>();
    reduce_kernel<<<(BB * NL * INNERD) / 256, 256>>>();
    // final: out = o @ Wout   (M=512, N=1024, K=512)
    gemm64_kernel<<<dim3(DD / 64, (BB * NL) / 64), 256>>>(p_o, Wout, out,
                                                          BB * NL, DD, INNERD, 1.0f);
}

// round 9
// speedup vs baseline: 2.7510x; 2.7510x over previous
#include <cuda_runtime.h>
#include <cuda_bf16.h>
#include <math.h>
#include <stdint.h>

// ---------------- problem constants ----------------
#define BB     8
#define FF     8192
#define NL     64
#define DD     1024
#define HH     8
#define DHD    64
#define INNERD 512
#define KVLEN  (FF + NL)        // 8256
#define MROWS  (BB * KVLEN)     // 66048 = 516 * 128
#define NSPLIT 16
#define CHUNK  528
#define QSCALE 0.125f
#define NEGINF -1e30f

// ---------------- scratch (device globals; no allocs allowed) ----------------
__device__ float g_latn[BB * NL * DD];
__device__ float g_q[BB * NL * INNERD];
__device__ float g_k[MROWS * INNERD];                 // fp32 K (for sim)
__device__ float g_v[MROWS * INNERD];                 // fp32 V (for pv)
__device__ float g_sim[BB * HH * NL * KVLEN];
__device__ float g_opart[NSPLIT * BB * NL * INNERD];
__device__ float g_o[BB * NL * INNERD];
__device__ int   g_mask_mode;
// bf16 split operands for the tensor-core KV GEMM
__device__ __align__(16) __nv_bfloat16 g_ahi[(size_t)MROWS * DD];   // 129 MB
__device__ __align__(16) __nv_bfloat16 g_alo[(size_t)MROWS * DD];   // 129 MB
__device__ __align__(16) __nv_bfloat16 g_bhi[2 * INNERD * DD];      // Wk|Wv transposed [N][K]
__device__ __align__(16) __nv_bfloat16 g_blo[2 * INNERD * DD];

// ================= low-level helpers (sm_80-era only; no 'a'-gated instrs) ==========
__device__ __forceinline__ uint32_t smem_to_u32(const void* p) {
    uint32_t a;
    asm("{ .reg .u64 t; cvta.to.shared.u64 t, %1; cvt.u32.u64 %0, t; }" : "=r"(a) : "l"(p));
    return a;
}
__device__ __forceinline__ void cp16(uint32_t s, const void* g) {
    asm volatile("cp.async.cg.shared.global [%0], [%1], 16;" :: "r"(s), "l"(g));
}
#define CP_COMMIT() asm volatile("cp.async.commit_group;" ::: "memory")
#define CP_WAIT1()  asm volatile("cp.async.wait_group 1;" ::: "memory")
#define CP_WAIT0()  asm volatile("cp.async.wait_group 0;" ::: "memory")
__device__ __forceinline__ void ldsm_x4(uint32_t* r, uint32_t addr) {
    asm volatile("ldmatrix.sync.aligned.m8n8.x4.shared.b16 {%0,%1,%2,%3}, [%4];"
                 : "=r"(r[0]), "=r"(r[1]), "=r"(r[2]), "=r"(r[3]) : "r"(addr));
}
__device__ __forceinline__ void mma_bf16(float* c, const uint32_t* a, const uint32_t* b) {
    asm volatile("mma.sync.aligned.m16n8k16.row.col.f32.bf16.bf16.f32 "
                 "{%0,%1,%2,%3}, {%4,%5,%6,%7}, {%8,%9}, {%0,%1,%2,%3};"
                 : "+f"(c[0]), "+f"(c[1]), "+f"(c[2]), "+f"(c[3])
                 : "r"(a[0]), "r"(a[1]), "r"(a[2]), "r"(a[3]), "r"(b[0]), "r"(b[1]));
}
__device__ __forceinline__ uint32_t pack_bf2(float a, float b) {
    __nv_bfloat162 t = __floats2bfloat162_rn(a, b);
    return *reinterpret_cast<uint32_t*>(&t);
}

// ---------------- mask dtype detection (proven in R7) ----------------
__global__ void detect_mask_kernel(const unsigned int* __restrict__ mw) {
    __shared__ unsigned int sh[2];
    if (threadIdx.x == 0) { sh[0] = 0u; sh[1] = 0u; }
    __syncthreads();
    unsigned int a1 = 0u, a3 = 0u;
    for (int i = threadIdx.x; i < 16384; i += 256) {
        unsigned int w = mw[i];
        a1 |= (w & 0x0000FF00u);
        a3 |= (w & 0xFF000000u);
    }
#pragma unroll
    for (int o = 16; o; o >>= 1) {
        a1 |= __shfl_xor_sync(0xffffffffu, a1, o);
        a3 |= __shfl_xor_sync(0xffffffffu, a3, o);
    }
    if ((threadIdx.x & 31) == 0) { atomicOr(&sh[0], a1); atomicOr(&sh[1], a3); }
    __syncthreads();
    if (threadIdx.x == 0) g_mask_mode = sh[0] ? 0 : (sh[1] ? 2 : 1);
}
__device__ __forceinline__ int mask_padded(const void* mask, int mode, int idx) {
    if (mode == 0) return ((const unsigned char*)mask)[idx] != 0;
    if (mode == 1) return ((const int*)mask)[idx] != 0;
    return ((const float*)mask)[idx] != 0.0f;
}

// ---------------- LN core (row of 1024, 256 threads) ----------
__device__ __forceinline__ float4 ln_row(const float* __restrict__ in,
                                         const float* __restrict__ gamma,
                                         const float* __restrict__ beta, int row, int t) {
    float4 v = reinterpret_cast<const float4*>(in + (size_t)row * DD)[t];
    float s  = (v.x + v.y) + (v.z + v.w);
    float ss = v.x * v.x + v.y * v.y + v.z * v.z + v.w * v.w;
    __shared__ float red[16];
    __shared__ float s_mu, s_rstd;
#pragma unroll
    for (int o = 16; o; o >>= 1) {
        s  += __shfl_xor_sync(0xffffffffu, s, o);
        ss += __shfl_xor_sync(0xffffffffu, ss, o);
    }
    if ((t & 31) == 0) { red[t >> 5] = s; red[(t >> 5) + 8] = ss; }
    __syncthreads();
    if (t < 8) {
        float a = red[t], b2 = red[t + 8];
#pragma unroll
        for (int o = 4; o; o >>= 1) {
            a  += __shfl_xor_sync(0xffu, a, o);
            b2 += __shfl_xor_sync(0xffu, b2, o);
        }
        if (t == 0) {
            float mu = a * (1.0f / DD);
            float var = b2 * (1.0f / DD) - mu * mu;
            s_mu = mu; s_rstd = rsqrtf(var + 1e-5f);
        }
    }
    __syncthreads();
    const float mu = s_mu, rstd = s_rstd;
    float4 g4 = reinterpret_cast<const float4*>(gamma)[t];
    float4 b4 = reinterpret_cast<const float4*>(beta)[t];
    float4 o4;
    o4.x = (v.x - mu) * rstd * g4.x + b4.x;
    o4.y = (v.y - mu) * rstd * g4.y + b4.y;
    o4.z = (v.z - mu) * rstd * g4.z + b4.z;
    o4.w = (v.w - mu) * rstd * g4.w + b4.w;
    return o4;
}

__device__ __forceinline__ void write_hilo(size_t elem, float a, float b, float c, float d) {
    float hf0 = __bfloat162float(__float2bfloat16(a));
    float hf1 = __bfloat162float(__float2bfloat16(b));
    float hf2 = __bfloat162float(__float2bfloat16(c));
    float hf3 = __bfloat162float(__float2bfloat16(d));
    uint2 hw = make_uint2(pack_bf2(hf0, hf1), pack_bf2(hf2, hf3));
    uint2 lw = make_uint2(pack_bf2(a - hf0, b - hf1), pack_bf2(c - hf2, d - hf3));
    *reinterpret_cast<uint2*>(g_ahi + elem) = hw;
    *reinterpret_cast<uint2*>(g_alo + elem) = lw;
}

// LN for x: writes bf16 hi/lo directly into KV-row layout
__global__ void __launch_bounds__(256) ln_x_kernel(const float* __restrict__ in,
                                                   const float* __restrict__ gamma,
                                                   const float* __restrict__ beta) {
    const int row = blockIdx.x;               // 0 .. BB*FF-1
    const int t = threadIdx.x;
    float4 o4 = ln_row(in, gamma, beta, row, t);
    const int b = row / FF, s = row - b * FF;
    const size_t kvrow = (size_t)b * KVLEN + s;
    write_hilo(kvrow * DD + t * 4, o4.x, o4.y, o4.z, o4.w);
}

// LN for latents: fp32 (ungated, for q GEMM) + gated bf16 hi/lo KV rows
__global__ void __launch_bounds__(256) ln_lat_kernel(const float* __restrict__ in,
                                                     const float* __restrict__ gamma,
                                                     const float* __restrict__ beta,
                                                     const float* __restrict__ gate_p,
                                                     float* __restrict__ outf) {
    const int row = blockIdx.x;               // 0 .. BB*NL-1
    const int t = threadIdx.x;
    float4 o4 = ln_row(in, gamma, beta, row, t);
    reinterpret_cast<float4*>(outf + (size_t)row * DD)[t] = o4;
    const float g = *gate_p;
    const int b = row / NL, l = row - b * NL;
    const size_t kvrow = (size_t)b * KVLEN + FF + l;
    write_hilo(kvrow * DD + t * 4, o4.x * g, o4.y * g, o4.z * g, o4.w * g);
}

// ---------------- W transpose + bf16 split: [K,N] fp32 -> [mat][N][K] bf16 hi/lo ----------
__global__ void __launch_bounds__(256) wtrans_kernel(const float* __restrict__ Wk,
                                                     const float* __restrict__ Wv) {
    __shared__ float tbuf[32][33];
    const int mat = blockIdx.z;
    const float* W = mat ? Wv : Wk;
    const int k0 = blockIdx.x * 32, n0 = blockIdx.y * 32;
    const int tx = threadIdx.x & 31, ty = threadIdx.x >> 5;   // 32 x 8
#pragma unroll
    for (int i = 0; i < 4; i++)
        tbuf[ty + 8 * i][tx] = W[(size_t)(k0 + ty + 8 * i) * INNERD + n0 + tx];
    __syncthreads();
#pragma unroll
    for (int i = 0; i < 4; i++) {
        const int n = n0 + ty + 8 * i, k = k0 + tx;
        float v = tbuf[tx][ty + 8 * i];
        __nv_bfloat16 hi = __float2bfloat16(v);
        float lo = v - __bfloat162float(hi);
        const size_t idx = ((size_t)mat * INNERD + n) * DD + k;
        g_bhi[idx] = hi;
        g_blo[idx] = __float2bfloat16(lo);
    }
}

// ---------------- KV GEMM on mma.sync (bf16 3-term split, fp32 accum) ----------------
// grid (8, 516): x -> 128-col slice {K:0..3, V:0..3}, y -> 128-row M block.
// CTA tile 128x128, BK=32, 8 warps (2m x 4n), warp tile 64x32 via m16n8k16.
#define BKK   32
#define APAD  40                 // 80B row stride: conflict-free ldmatrix
#define KVTILE (128 * APAD)      // 5120 bf16 elems per array per buffer
#define KV_SMEM_B (8 * KVTILE * 2)   // 81920 bytes (2 bufs x 4 arrays)

__global__ void __launch_bounds__(256, 1) kv_mma_kernel() {
    extern __shared__ __nv_bfloat16 sm[];
    const uint32_t sbase = smem_to_u32(sm);
    const int tid = threadIdx.x;
    const int lane = tid & 31, wid = tid >> 5;
    const int warp_m = wid >> 2, warp_n = wid & 3;
    const int nblk = blockIdx.x;
    const int m0 = blockIdx.y * 128;
    const int mat = nblk >> 2;
    const int n0 = (nblk & 3) * 128;
    const __nv_bfloat16* __restrict__ Bh = g_bhi + (size_t)mat * INNERD * DD;
    const __nv_bfloat16* __restrict__ Bl = g_blo + (size_t)mat * INNERD * DD;

    float acc[4][4][4];
#pragma unroll
    for (int i = 0; i < 4; i++)
#pragma unroll
        for (int j = 0; j < 4; j++)
#pragma unroll
            for (int q = 0; q < 4; q++) acc[i][j][q] = 0.f;

    // ---- async tile loader: arrays {0:Ahi, 1:Alo, 2:Bhi, 3:Blo}, each 128 rows x 32 k ----
#define KV_ISSUE(buf, k0)                                                             \
    do {                                                                              \
        const __nv_bfloat16* _src;                                                    \
        _Pragma("unroll")                                                             \
        for (int arr = 0; arr < 4; arr++) {                                           \
            _src = (arr == 0) ? g_ahi : (arr == 1) ? g_alo : (arr == 2) ? Bh : Bl;    \
            const int rbase = (arr < 2) ? m0 : n0;                                    \
            _Pragma("unroll")                                                         \
            for (int i = 0; i < 2; i++) {                                             \
                int id = tid + 256 * i;            /* 0..511 */                       \
                int row = id >> 2, c4 = id & 3;                                       \
                const __nv_bfloat16* gp = _src + (size_t)(rbase + row) * DD + (k0) + c4 * 8; \
                uint32_t sp = sbase + (((buf) * 4 + arr) * KVTILE + row * APAD + c4 * 8) * 2; \
                cp16(sp, gp);                                                         \
            }                                                                         \
        }                                                                             \
    } while (0)

    KV_ISSUE(0, 0);
    CP_COMMIT();

    for (int c = 0; c < DD / BKK; c++) {
        const int buf = c & 1;
        if (c < DD / BKK - 1) {
            KV_ISSUE(buf ^ 1, (c + 1) * BKK);
            CP_COMMIT();
            CP_WAIT1();
        } else {
            CP_WAIT0();
        }
        __syncthreads();

        const uint32_t ab = sbase + ((buf * 4 + 0) * KVTILE) * 2;
        const uint32_t lb = sbase + ((buf * 4 + 1) * KVTILE) * 2;
        const uint32_t bb = sbase + ((buf * 4 + 2) * KVTILE) * 2;
        const uint32_t vb = sbase + ((buf * 4 + 3) * KVTILE) * 2;
#pragma unroll
        for (int ks = 0; ks < 2; ks++) {
            const int koff = ks * 16;
            uint32_t ah[4][4], al[4][4];
#pragma unroll
            for (int mt = 0; mt < 4; mt++) {
                const uint32_t ro = ((warp_m * 64 + mt * 16 + (lane & 15)) * APAD
                                     + koff + (lane >> 4) * 8) * 2;
                ldsm_x4(ah[mt], ab + ro);
                ldsm_x4(al[mt], lb + ro);
            }
            uint32_t bh[4][2], bl[4][2];
#pragma unroll
            for (int p = 0; p < 2; p++) {
                const int g2 = lane >> 3;                       // 0..3
                const uint32_t ro = ((warp_n * 32 + p * 16 + (g2 >> 1) * 8 + (lane & 7)) * APAD
                                     + koff + (g2 & 1) * 8) * 2;
                uint32_t r[4];
                ldsm_x4(r, bb + ro);
                bh[2 * p][0] = r[0]; bh[2 * p][1] = r[1];
                bh[2 * p + 1][0] = r[2]; bh[2 * p + 1][1] = r[3];
                ldsm_x4(r, vb + ro);
                bl[2 * p][0] = r[0]; bl[2 * p][1] = r[1];
                bl[2 * p + 1][0] = r[2]; bl[2 * p + 1][1] = r[3];
            }
            // term-major ordering: same-acc RAW 16 MMAs apart
#pragma unroll
            for (int mt = 0; mt < 4; mt++)
#pragma unroll
                for (int nt = 0; nt < 4; nt++) mma_bf16(acc[mt][nt], ah[mt], bh[nt]);
#pragma unroll
            for (int mt = 0; mt < 4; mt++)
#pragma unroll
                for (int nt = 0; nt < 4; nt++) mma_bf16(acc[mt][nt], ah[mt], bl[nt]);
#pragma unroll
            for (int mt = 0; mt < 4; mt++)
#pragma unroll
                for (int nt = 0; nt < 4; nt++) mma_bf16(acc[mt][nt], al[mt], bh[nt]);
        }
        __syncthreads();
    }

    float* __restrict__ dst = mat ? g_v : g_k;
#pragma unroll
    for (int mt = 0; mt < 4; mt++) {
        const int r0 = m0 + warp_m * 64 + mt * 16 + (lane >> 2);
#pragma unroll
        for (int nt = 0; nt < 4; nt++) {
            const int cc = n0 + warp_n * 32 + nt * 8 + (lane & 3) * 2;
            *reinterpret_cast<float2*>(&dst[(size_t)r0 * INNERD + cc]) =
                make_float2(acc[mt][nt][0], acc[mt][nt][1]);
            *reinterpret_cast<float2*>(&dst[(size_t)(r0 + 8) * INNERD + cc]) =
                make_float2(acc[mt][nt][2], acc[mt][nt][3]);
        }
    }
}

// ---------------- generic small GEMM: C = alpha * A[MxK] @ B[KxN], 64x64 tiles ----------------
__global__ void __launch_bounds__(256) gemm64_kernel(const float* __restrict__ A,
                                                     const float* __restrict__ Bm,
                                                     float* __restrict__ C,
                                                     int M, int N, int K, float alpha) {
    __shared__ float As[16][68];
    __shared__ float Bs[16][64];
    const int t  = threadIdx.x;
    const int m0 = blockIdx.y * 64, n0 = blockIdx.x * 64;
    const int tx = t & 15, ty = t >> 4;
    const int arow = t >> 2, ak = (t & 3) * 4;
    const int brow = t >> 4, bc = (t & 15) * 4;
    float acc[4][4];
#pragma unroll
    for (int i = 0; i < 4; i++)
#pragma unroll
        for (int j = 0; j < 4; j++) acc[i][j] = 0.f;

    for (int k0 = 0; k0 < K; k0 += 16) {
        float4 a4 = *reinterpret_cast<const float4*>(A + (size_t)(m0 + arow) * K + k0 + ak);
        As[ak + 0][arow] = a4.x;
        As[ak + 1][arow] = a4.y;
        As[ak + 2][arow] = a4.z;
        As[ak + 3][arow] = a4.w;
        *reinterpret_cast<float4*>(&Bs[brow][bc]) =
            *reinterpret_cast<const float4*>(Bm + (size_t)(k0 + brow) * N + n0 + bc);
        __syncthreads();
#pragma unroll
        for (int k = 0; k < 16; k++) {
            float af[4], bf[4];
            *reinterpret_cast<float4*>(&af[0]) = *reinterpret_cast<const float4*>(&As[k][ty * 4]);
            *reinterpret_cast<float4*>(&bf[0]) = *reinterpret_cast<const float4*>(&Bs[k][tx * 4]);
#pragma unroll
            for (int i = 0; i < 4; i++)
#pragma unroll
                for (int j = 0; j < 4; j++) acc[i][j] += af[i] * bf[j];
        }
        __syncthreads();
    }
#pragma unroll
    for (int i = 0; i < 4; i++)
        *reinterpret_cast<float4*>(&C[(size_t)(m0 + ty * 4 + i) * N + n0 + tx * 4]) =
            make_float4(acc[i][0] * alpha, acc[i][1] * alpha, acc[i][2] * alpha, acc[i][3] * alpha);
}

// ---------------- sim = (q*SCALE) @ k^T per (b,h), fused padding mask ----------------
__global__ void __launch_bounds__(256) sim_kernel(const void* __restrict__ mask) {
    __shared__ float Qs[16][64];
    __shared__ float Ks[16][132];
    const int t   = threadIdx.x;
    const int bh  = blockIdx.y;
    const int b   = bh >> 3, h = bh & 7;
    const int kv0 = blockIdx.x * 128;
    const int tx = t & 15, ty = t >> 4;
    const int lrow = t >> 2, ld = (t & 3) * 4;

    float acc[4][8];
#pragma unroll
    for (int i = 0; i < 4; i++)
#pragma unroll
        for (int j = 0; j < 8; j++) acc[i][j] = 0.f;

    const float* qbase = g_q + (size_t)b * NL * INNERD + h * DHD;
    const float* kbase = g_k + (size_t)b * KVLEN * INNERD + h * DHD;

    for (int d0 = 0; d0 < DHD; d0 += 16) {
        float4 q4 = *reinterpret_cast<const float4*>(qbase + (size_t)lrow * INNERD + d0 + ld);
        Qs[ld + 0][lrow] = q4.x;
        Qs[ld + 1][lrow] = q4.y;
        Qs[ld + 2][lrow] = q4.z;
        Qs[ld + 3][lrow] = q4.w;
#pragma unroll
        for (int i = 0; i < 2; i++) {
            int kr = kv0 + lrow + 64 * i;
            float4 k4 = make_float4(0.f, 0.f, 0.f, 0.f);
            if (kr < KVLEN)
                k4 = *reinterpret_cast<const float4*>(kbase + (size_t)kr * INNERD + d0 + ld);
            Ks[ld + 0][lrow + 64 * i] = k4.x;
            Ks[ld + 1][lrow + 64 * i] = k4.y;
            Ks[ld + 2][lrow + 64 * i] = k4.z;
            Ks[ld + 3][lrow + 64 * i] = k4.w;
        }
        __syncthreads();
#pragma unroll
        for (int k = 0; k < 16; k++) {
            float qf[4], kf[8];
            *reinterpret_cast<float4*>(&qf[0]) = *reinterpret_cast<const float4*>(&Qs[k][ty * 4]);
            *reinterpret_cast<float4*>(&kf[0]) = *reinterpret_cast<const float4*>(&Ks[k][tx * 8]);
            *reinterpret_cast<float4*>(&kf[4]) = *reinterpret_cast<const float4*>(&Ks[k][tx * 8 + 4]);
#pragma unroll
            for (int i = 0; i < 4; i++)
#pragma unroll
                for (int j = 0; j < 8; j++) acc[i][j] += qf[i] * kf[j];
        }
        __syncthreads();
    }

    const int kvb = kv0 + tx * 8;
    if (kvb < KVLEN) {
        const int mode = g_mask_mode;
        int inval[8];
#pragma unroll
        for (int j = 0; j < 8; j++) {
            int kv = kvb + j;
            inval[j] = (kv < FF) && mask_padded(mask, mode, b * FF + kv);
        }
#pragma unroll
        for (int i = 0; i < 4; i++) {
            int q = ty * 4 + i;
            float* dst = g_sim + ((size_t)bh * NL + q) * KVLEN + kvb;
            float o[8];
#pragma unroll
            for (int j = 0; j < 8; j++) o[j] = inval[j] ? NEGINF : acc[i][j];
            *reinterpret_cast<float4*>(&dst[0]) = *reinterpret_cast<float4*>(&o[0]);
            *reinterpret_cast<float4*>(&dst[4]) = *reinterpret_cast<float4*>(&o[4]);
        }
    }
}

// ---------------- softmax over rows of g_sim (4096 rows x 8256), in place ----------------
__global__ void __launch_bounds__(256) softmax_kernel() {
    const int row = blockIdx.x;
    const int t = threadIdx.x;
    float* p = g_sim + (size_t)row * KVLEN;
    const int NV = KVLEN / 4;
    float4 v[9];
    float m = -3.4e38f;
#pragma unroll
    for (int i = 0; i < 9; i++) {
        int idx = t + 256 * i;
        if (idx < NV) {
            v[i] = *(reinterpret_cast<const float4*>(p) + idx);
            m = fmaxf(m, fmaxf(fmaxf(v[i].x, v[i].y), fmaxf(v[i].z, v[i].w)));
        }
    }
    __shared__ float red[8];
    __shared__ float s_max, s_sum;
#pragma unroll
    for (int o = 16; o; o >>= 1) m = fmaxf(m, __shfl_xor_sync(0xffffffffu, m, o));
    if ((t & 31) == 0) red[t >> 5] = m;
    __syncthreads();
    if (t < 8) {
        float a = red[t];
#pragma unroll
        for (int o = 4; o; o >>= 1) a = fmaxf(a, __shfl_xor_sync(0xffu, a, o));
        if (t == 0) s_max = a;
    }
    __syncthreads();
    m = s_max;
    float s = 0.f;
#pragma unroll
    for (int i = 0; i < 9; i++) {
        int idx = t + 256 * i;
        if (idx < NV) {
            v[i].x = __expf(v[i].x - m);
            v[i].y = __expf(v[i].y - m);
            v[i].z = __expf(v[i].z - m);
            v[i].w = __expf(v[i].w - m);
            s += (v[i].x + v[i].y) + (v[i].z + v[i].w);
        }
    }
#pragma unroll
    for (int o = 16; o; o >>= 1) s += __shfl_xor_sync(0xffffffffu, s, o);
    __syncthreads();
    if ((t & 31) == 0) red[t >> 5] = s;
    __syncthreads();
    if (t < 8) {
        float a = red[t];
#pragma unroll
        for (int o = 4; o; o >>= 1) a += __shfl_xor_sync(0xffu, a, o);
        if (t == 0) s_sum = a;
    }
    __syncthreads();
    const float r = 1.0f / s_sum;
#pragma unroll
    for (int i = 0; i < 9; i++) {
        int idx = t + 256 * i;
        if (idx < NV)
            *(reinterpret_cast<float4*>(p) + idx) =
                make_float4(v[i].x * r, v[i].y * r, v[i].z * r, v[i].w * r);
    }
}

// ---------------- attn @ v, split-K over kv into NSPLIT deterministic partials ----------------
__global__ void __launch_bounds__(256) pv_kernel() {
    const int split = blockIdx.x, bh = blockIdx.y;
    const int b = bh >> 3, h = bh & 7;
    const int kvs = split * CHUNK;
    const int kve = min(kvs + CHUNK, KVLEN);
    __shared__ float Ps[16][68];
    __shared__ float Vs[16][68];
    const int t = threadIdx.x;
    const int tx = t & 15, ty = t >> 4;
    const int prow = t >> 2, pk = (t & 3) * 4;
    const int vrow = t >> 4, vd = (t & 15) * 4;
    float acc[4][4];
#pragma unroll
    for (int i = 0; i < 4; i++)
#pragma unroll
        for (int j = 0; j < 4; j++) acc[i][j] = 0.f;

    const float* pbase = g_sim + (size_t)bh * NL * KVLEN;
    const float* vbase = g_v + (size_t)b * KVLEN * INNERD + h * DHD;

    for (int k0 = kvs; k0 < kve; k0 += 16) {
        float4 a4 = *reinterpret_cast<const float4*>(pbase + (size_t)prow * KVLEN + k0 + pk);
        Ps[pk + 0][prow] = a4.x;
        Ps[pk + 1][prow] = a4.y;
        Ps[pk + 2][prow] = a4.z;
        Ps[pk + 3][prow] = a4.w;
        *reinterpret_cast<float4*>(&Vs[vrow][vd]) =
            *reinterpret_cast<const float4*>(vbase + (size_t)(k0 + vrow) * INNERD + vd);
        __syncthreads();
#pragma unroll
        for (int k = 0; k < 16; k++) {
            float pf[4], vf[4];
            *reinterpret_cast<float4*>(&pf[0]) = *reinterpret_cast<const float4*>(&Ps[k][ty * 4]);
            *reinterpret_cast<float4*>(&vf[0]) = *reinterpret_cast<const float4*>(&Vs[k][tx * 4]);
#pragma unroll
            for (int i = 0; i < 4; i++)
#pragma unroll
                for (int j = 0; j < 4; j++) acc[i][j] += pf[i] * vf[j];
        }
        __syncthreads();
    }

    float* obase = g_opart + (size_t)split * (BB * NL * INNERD)
                 + (size_t)(b * NL) * INNERD + h * DHD;
#pragma unroll
    for (int i = 0; i < 4; i++)
        *reinterpret_cast<float4*>(&obase[(size_t)(ty * 4 + i) * INNERD + tx * 4]) =
            make_float4(acc[i][0], acc[i][1], acc[i][2], acc[i][3]);
}

// ---------------- deterministic split-K reduction ----------------
__global__ void __launch_bounds__(256) reduce_kernel() {
    const int i = blockIdx.x * blockDim.x + threadIdx.x;
    float s = 0.f;
#pragma unroll
    for (int k = 0; k < NSPLIT; k++) s += g_opart[(size_t)k * (BB * NL * INNERD) + i];
    g_o[i] = s;
}

// ---------------- launch ----------------
extern "C" void kernel_launch(void* const* d_in, const int* in_sizes, int n_in,
                              void* d_out, int out_size) {
    const float* x    = (const float*)d_in[0];
    const float* lat  = (const float*)d_in[1];
    const void*  mask = d_in[2];
    const float* gate = (const float*)d_in[3];
    const float* gm   = (const float*)d_in[4];
    const float* bm   = (const float*)d_in[5];
    const float* gl   = (const float*)d_in[6];
    const float* bl   = (const float*)d_in[7];
    const float* Wq   = (const float*)d_in[8];
    const float* Wk   = (const float*)d_in[9];
    const float* Wv   = (const float*)d_in[10];
    const float* Wout = (const float*)d_in[11];
    float* out = (float*)d_out;

    float *p_latn, *p_q, *p_o;
    cudaGetSymbolAddress((void**)&p_latn, g_latn);
    cudaGetSymbolAddress((void**)&p_q,    g_q);
    cudaGetSymbolAddress((void**)&p_o,    g_o);

    cudaFuncSetAttribute(kv_mma_kernel, cudaFuncAttributeMaxDynamicSharedMemorySize, KV_SMEM_B);

    detect_mask_kernel<<<1, 256>>>((const unsigned int*)mask);
    ln_x_kernel<<<BB * FF, 256>>>(x, gm, bm);
    ln_lat_kernel<<<BB * NL, 256>>>(lat, gl, bl, gate, p_latn);
    wtrans_kernel<<<dim3(DD / 32, INNERD / 32, 2), 256>>>(Wk, Wv);
    // q = LN(latents) @ Wq * SCALE
    gemm64_kernel<<<dim3(INNERD / 64, (BB * NL) / 64), 256>>>(p_latn, Wq, p_q,
                                                              BB * NL, INNERD, DD, QSCALE);
    // k,v on mma.sync tensor cores (bf16 3-term split, fp32 accum)
    kv_mma_kernel<<<dim3(8, MROWS / 128), 256, KV_SMEM_B>>>();
    // attention
    sim_kernel<<<dim3((KVLEN + 127) / 128, BB * HH), 256>>>(mask);
    softmax_kernel<<<BB * HH * NL, 256>>>();
    pv_kernel<<<dim3(NSPLIT, BB * HH), 256>>>();
    reduce_kernel<<<(BB * NL * INNERD) / 256, 256>>>();
    // out = o @ Wout
    gemm64_kernel<<<dim3(DD / 64, (BB * NL) / 64), 256>>>(p_o, Wout, out,
                                                          BB * NL, DD, INNERD, 1.0f);
}

// round 11
// speedup vs baseline: 2.7957x; 1.0162x over previous
#include <cuda_runtime.h>
#include <cuda_bf16.h>
#include <math.h>
#include <stdint.h>

// ---------------- problem constants ----------------
#define BB     8
#define FF     8192
#define NL     64
#define DD     1024
#define HH     8
#define DHD    64
#define INNERD 512
#define KVLEN  (FF + NL)        // 8256
#define MROWS  (BB * KVLEN)     // 66048 = 516 * 128
#define NSPLIT 16
#define CHUNK  528
#define QSCALE 0.125f
#define NEGINF -1e30f

// ---------------- scratch (device globals; no allocs allowed) ----------------
__device__ float g_q[BB * NL * INNERD];
__device__ float g_k[MROWS * INNERD];                 // fp32 K (for sim)
__device__ float g_v[MROWS * INNERD];                 // fp32 V (for pv)
__device__ float g_sim[BB * HH * NL * KVLEN];
__device__ float g_opart[NSPLIT * BB * NL * INNERD];
__device__ int   g_mask_mode;
// bf16 split operands
__device__ __align__(16) __nv_bfloat16 g_ahi[(size_t)MROWS * DD];   // KV-rows A hi
__device__ __align__(16) __nv_bfloat16 g_alo[(size_t)MROWS * DD];   // KV-rows A lo
__device__ __align__(16) __nv_bfloat16 g_bhi[2 * INNERD * DD];      // Wk|Wv ^T [N][K]
__device__ __align__(16) __nv_bfloat16 g_blo[2 * INNERD * DD];
__device__ __align__(16) __nv_bfloat16 g_lathi[BB * NL * DD];       // LN(lat) ungated
__device__ __align__(16) __nv_bfloat16 g_latlo[BB * NL * DD];
__device__ __align__(16) __nv_bfloat16 g_wqhi[INNERD * DD];         // Wq^T [512][1024]
__device__ __align__(16) __nv_bfloat16 g_wqlo[INNERD * DD];
__device__ __align__(16) __nv_bfloat16 g_wohi[DD * INNERD];         // Wout^T [1024][512]
__device__ __align__(16) __nv_bfloat16 g_wolo[DD * INNERD];
__device__ __align__(16) __nv_bfloat16 g_ohi[BB * NL * INNERD];     // attn@v hi/lo
__device__ __align__(16) __nv_bfloat16 g_olo[BB * NL * INNERD];

// ================= low-level helpers (sm_80-era only) ==========
__device__ __forceinline__ uint32_t smem_to_u32(const void* p) {
    uint32_t a;
    asm("{ .reg .u64 t; cvta.to.shared.u64 t, %1; cvt.u32.u64 %0, t; }" : "=r"(a) : "l"(p));
    return a;
}
__device__ __forceinline__ void cp16(uint32_t s, const void* g) {
    asm volatile("cp.async.cg.shared.global [%0], [%1], 16;" :: "r"(s), "l"(g));
}
#define CP_COMMIT() asm volatile("cp.async.commit_group;" ::: "memory")
#define CP_WAIT2()  asm volatile("cp.async.wait_group 2;" ::: "memory")
#define CP_WAIT1()  asm volatile("cp.async.wait_group 1;" ::: "memory")
#define CP_WAIT0()  asm volatile("cp.async.wait_group 0;" ::: "memory")
__device__ __forceinline__ void ldsm_x4(uint32_t* r, uint32_t addr) {
    asm volatile("ldmatrix.sync.aligned.m8n8.x4.shared.b16 {%0,%1,%2,%3}, [%4];"
                 : "=r"(r[0]), "=r"(r[1]), "=r"(r[2]), "=r"(r[3]) : "r"(addr));
}
__device__ __forceinline__ void mma_bf16(float* c, const uint32_t* a, const uint32_t* b) {
    asm volatile("mma.sync.aligned.m16n8k16.row.col.f32.bf16.bf16.f32 "
                 "{%0,%1,%2,%3}, {%4,%5,%6,%7}, {%8,%9}, {%0,%1,%2,%3};"
                 : "+f"(c[0]), "+f"(c[1]), "+f"(c[2]), "+f"(c[3])
                 : "r"(a[0]), "r"(a[1]), "r"(a[2]), "r"(a[3]), "r"(b[0]), "r"(b[1]));
}
__device__ __forceinline__ uint32_t pack_bf2(float a, float b) {
    __nv_bfloat162 t = __floats2bfloat162_rn(a, b);
    return *reinterpret_cast<uint32_t*>(&t);
}

// ---------------- mask dtype detection (proven) ----------------
__global__ void detect_mask_kernel(const unsigned int* __restrict__ mw) {
    __shared__ unsigned int sh[2];
    if (threadIdx.x == 0) { sh[0] = 0u; sh[1] = 0u; }
    __syncthreads();
    unsigned int a1 = 0u, a3 = 0u;
    for (int i = threadIdx.x; i < 16384; i += 256) {
        unsigned int w = mw[i];
        a1 |= (w & 0x0000FF00u);
        a3 |= (w & 0xFF000000u);
    }
#pragma unroll
    for (int o = 16; o; o >>= 1) {
        a1 |= __shfl_xor_sync(0xffffffffu, a1, o);
        a3 |= __shfl_xor_sync(0xffffffffu, a3, o);
    }
    if ((threadIdx.x & 31) == 0) { atomicOr(&sh[0], a1); atomicOr(&sh[1], a3); }
    __syncthreads();
    if (threadIdx.x == 0) g_mask_mode = sh[0] ? 0 : (sh[1] ? 2 : 1);
}
__device__ __forceinline__ int mask_padded(const void* mask, int mode, int idx) {
    if (mode == 0) return ((const unsigned char*)mask)[idx] != 0;
    if (mode == 1) return ((const int*)mask)[idx] != 0;
    return ((const float*)mask)[idx] != 0.0f;
}

// ---------------- LN core ----------
__device__ __forceinline__ float4 ln_row(const float* __restrict__ in,
                                         const float* __restrict__ gamma,
                                         const float* __restrict__ beta, int row, int t) {
    float4 v = reinterpret_cast<const float4*>(in + (size_t)row * DD)[t];
    float s  = (v.x + v.y) + (v.z + v.w);
    float ss = v.x * v.x + v.y * v.y + v.z * v.z + v.w * v.w;
    __shared__ float red[16];
    __shared__ float s_mu, s_rstd;
#pragma unroll
    for (int o = 16; o; o >>= 1) {
        s  += __shfl_xor_sync(0xffffffffu, s, o);
        ss += __shfl_xor_sync(0xffffffffu, ss, o);
    }
    if ((t & 31) == 0) { red[t >> 5] = s; red[(t >> 5) + 8] = ss; }
    __syncthreads();
    if (t < 8) {
        float a = red[t], b2 = red[t + 8];
#pragma unroll
        for (int o = 4; o; o >>= 1) {
            a  += __shfl_xor_sync(0xffu, a, o);
            b2 += __shfl_xor_sync(0xffu, b2, o);
        }
        if (t == 0) {
            float mu = a * (1.0f / DD);
            float var = b2 * (1.0f / DD) - mu * mu;
            s_mu = mu; s_rstd = rsqrtf(var + 1e-5f);
        }
    }
    __syncthreads();
    const float mu = s_mu, rstd = s_rstd;
    float4 g4 = reinterpret_cast<const float4*>(gamma)[t];
    float4 b4 = reinterpret_cast<const float4*>(beta)[t];
    float4 o4;
    o4.x = (v.x - mu) * rstd * g4.x + b4.x;
    o4.y = (v.y - mu) * rstd * g4.y + b4.y;
    o4.z = (v.z - mu) * rstd * g4.z + b4.z;
    o4.w = (v.w - mu) * rstd * g4.w + b4.w;
    return o4;
}

__device__ __forceinline__ void write_hilo_to(__nv_bfloat16* hp, __nv_bfloat16* lp,
                                              size_t elem, float a, float b, float c, float d) {
    float hf0 = __bfloat162float(__float2bfloat16(a));
    float hf1 = __bfloat162float(__float2bfloat16(b));
    float hf2 = __bfloat162float(__float2bfloat16(c));
    float hf3 = __bfloat162float(__float2bfloat16(d));
    uint2 hw = make_uint2(pack_bf2(hf0, hf1), pack_bf2(hf2, hf3));
    uint2 lw = make_uint2(pack_bf2(a - hf0, b - hf1), pack_bf2(c - hf2, d - hf3));
    *reinterpret_cast<uint2*>(hp + elem) = hw;
    *reinterpret_cast<uint2*>(lp + elem) = lw;
}

// LN for x: bf16 hi/lo into KV-row layout
__global__ void __launch_bounds__(256) ln_x_kernel(const float* __restrict__ in,
                                                   const float* __restrict__ gamma,
                                                   const float* __restrict__ beta) {
    const int row = blockIdx.x;
    const int t = threadIdx.x;
    float4 o4 = ln_row(in, gamma, beta, row, t);
    const int b = row / FF, s = row - b * FF;
    const size_t kvrow = (size_t)b * KVLEN + s;
    write_hilo_to(g_ahi, g_alo, kvrow * DD + t * 4, o4.x, o4.y, o4.z, o4.w);
}

// LN for latents: ungated hi/lo (q GEMM A) + gated hi/lo KV rows
__global__ void __launch_bounds__(256) ln_lat_kernel(const float* __restrict__ in,
                                                     const float* __restrict__ gamma,
                                                     const float* __restrict__ beta,
                                                     const float* __restrict__ gate_p) {
    const int row = blockIdx.x;               // 0 .. BB*NL-1
    const int t = threadIdx.x;
    float4 o4 = ln_row(in, gamma, beta, row, t);
    write_hilo_to(g_lathi, g_latlo, (size_t)row * DD + t * 4, o4.x, o4.y, o4.z, o4.w);
    const float g = *gate_p;
    const int b = row / NL, l = row - b * NL;
    const size_t kvrow = (size_t)b * KVLEN + FF + l;
    write_hilo_to(g_ahi, g_alo, kvrow * DD + t * 4, o4.x * g, o4.y * g, o4.z * g, o4.w * g);
}

// ---------------- W transpose + bf16 split: [Kdim][Ndim] fp32 -> [Ndim][Kdim] hi/lo ------
__global__ void __launch_bounds__(256) wtrans_kernel(const float* __restrict__ W,
                                                     __nv_bfloat16* __restrict__ dhi,
                                                     __nv_bfloat16* __restrict__ dlo,
                                                     int Kdim, int Ndim) {
    __shared__ float tbuf[32][33];
    const int k0 = blockIdx.x * 32, n0 = blockIdx.y * 32;
    const int tx = threadIdx.x & 31, ty = threadIdx.x >> 5;   // 32 x 8
#pragma unroll
    for (int i = 0; i < 4; i++)
        tbuf[ty + 8 * i][tx] = W[(size_t)(k0 + ty + 8 * i) * Ndim + n0 + tx];
    __syncthreads();
#pragma unroll
    for (int i = 0; i < 4; i++) {
        const int n = n0 + ty + 8 * i, k = k0 + tx;
        float v = tbuf[tx][ty + 8 * i];
        __nv_bfloat16 hi = __float2bfloat16(v);
        float lo = v - __bfloat162float(hi);
        const size_t idx = (size_t)n * Kdim + k;
        dhi[idx] = hi;
        dlo[idx] = __float2bfloat16(lo);
    }
}

// ================= generic bf16-split MMA GEMM =================
// C[M x N] = alpha * A[M x K] @ B[N x K]^T   (A,B as hi/lo bf16; 3-term split, fp32 acc)
// Tile 128x128, BK=32, 3-stage cp.async, 8 warps (2m x 4n), warp 64x32 m16n8k16.
#define BKK    32
#define APAD   40                    // 80B row stride: conflict-free ldmatrix
#define KVTILE (128 * APAD)          // bf16 elems per array per stage
#define MMA_SMEM (12 * KVTILE * 2)   // 3 stages x 4 arrays = 122880 B

__device__ __forceinline__ void issue_tiles(uint32_t sbase, int buf,
                                            const __nv_bfloat16* __restrict__ Ah,
                                            const __nv_bfloat16* __restrict__ Al,
                                            const __nv_bfloat16* __restrict__ Bh,
                                            const __nv_bfloat16* __restrict__ Bl,
                                            int m0, int n0, int k0, int strideK, int tid) {
#pragma unroll
    for (int arr = 0; arr < 4; arr++) {
        const __nv_bfloat16* src = (arr == 0) ? Ah : (arr == 1) ? Al : (arr == 2) ? Bh : Bl;
        const int rbase = (arr < 2) ? m0 : n0;
#pragma unroll
        for (int i = 0; i < 2; i++) {
            int id = tid + 256 * i;                 // 0..511
            int row = id >> 2, c4 = id & 3;
            const __nv_bfloat16* gp = src + (size_t)(rbase + row) * strideK + k0 + c4 * 8;
            uint32_t sp = sbase + ((buf * 4 + arr) * KVTILE + row * APAD + c4 * 8) * 2;
            cp16(sp, gp);
        }
    }
}

__device__ __forceinline__ void compute_chunk(uint32_t sbase, int buf,
                                              int warp_m, int warp_n, int lane,
                                              float (&acc)[4][4][4]) {
    const uint32_t ab = sbase + ((buf * 4 + 0) * KVTILE) * 2;
    const uint32_t lb = sbase + ((buf * 4 + 1) * KVTILE) * 2;
    const uint32_t bb = sbase + ((buf * 4 + 2) * KVTILE) * 2;
    const uint32_t vb = sbase + ((buf * 4 + 3) * KVTILE) * 2;
#pragma unroll
    for (int ks = 0; ks < 2; ks++) {
        const int koff = ks * 16;
        uint32_t ah[4][4], al[4][4];
#pragma unroll
        for (int mt = 0; mt < 4; mt++) {
            const uint32_t ro = ((warp_m * 64 + mt * 16 + (lane & 15)) * APAD
                                 + koff + (lane >> 4) * 8) * 2;
            ldsm_x4(ah[mt], ab + ro);
            ldsm_x4(al[mt], lb + ro);
        }
        uint32_t bh[4][2], bl[4][2];
#pragma unroll
        for (int p = 0; p < 2; p++) {
            const int g2 = lane >> 3;               // 0..3
            const uint32_t ro = ((warp_n * 32 + p * 16 + (g2 >> 1) * 8 + (lane & 7)) * APAD
                                 + koff + (g2 & 1) * 8) * 2;
            uint32_t r[4];
            ldsm_x4(r, bb + ro);
            bh[2 * p][0] = r[0]; bh[2 * p][1] = r[1];
            bh[2 * p + 1][0] = r[2]; bh[2 * p + 1][1] = r[3];
            ldsm_x4(r, vb + ro);
            bl[2 * p][0] = r[0]; bl[2 * p][1] = r[1];
            bl[2 * p + 1][0] = r[2]; bl[2 * p + 1][1] = r[3];
        }
        // term-major ordering: same-acc RAW 16 MMAs apart
#pragma unroll
        for (int mt = 0; mt < 4; mt++)
#pragma unroll
            for (int nt = 0; nt < 4; nt++) mma_bf16(acc[mt][nt], ah[mt], bh[nt]);
#pragma unroll
        for (int mt = 0; mt < 4; mt++)
#pragma unroll
            for (int nt = 0; nt < 4; nt++) mma_bf16(acc[mt][nt], ah[mt], bl[nt]);
#pragma unroll
        for (int mt = 0; mt < 4; mt++)
#pragma unroll
            for (int nt = 0; nt < 4; nt++) mma_bf16(acc[mt][nt], al[mt], bh[nt]);
    }
}

__global__ void __launch_bounds__(256, 1) mma_gemm_kernel(
    const __nv_bfloat16* __restrict__ Ah, const __nv_bfloat16* __restrict__ Al,
    const __nv_bfloat16* __restrict__ Bh, const __nv_bfloat16* __restrict__ Bl,
    float* __restrict__ C, int K, int ldc, float alpha) {
    extern __shared__ __nv_bfloat16 sm[];
    const uint32_t sbase = smem_to_u32(sm);
    const int tid = threadIdx.x;
    const int lane = tid & 31, wid = tid >> 5;
    const int warp_m = wid >> 2, warp_n = wid & 3;
    const int m0 = blockIdx.y * 128, n0 = blockIdx.x * 128;

    float acc[4][4][4];
#pragma unroll
    for (int i = 0; i < 4; i++)
#pragma unroll
        for (int j = 0; j < 4; j++)
#pragma unroll
            for (int q = 0; q < 4; q++) acc[i][j][q] = 0.f;

    const int NITER = K / BKK;      // >= 16 for all call sites
    issue_tiles(sbase, 0, Ah, Al, Bh, Bl, m0, n0, 0, K, tid);
    CP_COMMIT();
    issue_tiles(sbase, 1, Ah, Al, Bh, Bl, m0, n0, BKK, K, tid);
    CP_COMMIT();

    for (int c = 0; c < NITER; c++) {
        const int buf = c % 3;
        if (c + 2 < NITER) {
            issue_tiles(sbase, (c + 2) % 3, Ah, Al, Bh, Bl, m0, n0, (c + 2) * BKK, K, tid);
            CP_COMMIT();
            CP_WAIT2();
        } else if (c + 1 < NITER) {
            CP_WAIT1();
        } else {
            CP_WAIT0();
        }
        __syncthreads();
        compute_chunk(sbase, buf, warp_m, warp_n, lane, acc);
        __syncthreads();
    }

#pragma unroll
    for (int mt = 0; mt < 4; mt++) {
        const int r0 = m0 + warp_m * 64 + mt * 16 + (lane >> 2);
#pragma unroll
        for (int nt = 0; nt < 4; nt++) {
            const int cc = n0 + warp_n * 32 + nt * 8 + (lane & 3) * 2;
            *reinterpret_cast<float2*>(&C[(size_t)r0 * ldc + cc]) =
                make_float2(acc[mt][nt][0] * alpha, acc[mt][nt][1] * alpha);
            *reinterpret_cast<float2*>(&C[(size_t)(r0 + 8) * ldc + cc]) =
                make_float2(acc[mt][nt][2] * alpha, acc[mt][nt][3] * alpha);
        }
    }
}

// ---------------- sim = (q*SCALE) @ k^T per (b,h), fused padding mask ----------------
__global__ void __launch_bounds__(256) sim_kernel(const void* __restrict__ mask) {
    __shared__ float Qs[16][64];
    __shared__ float Ks[16][132];
    const int t   = threadIdx.x;
    const int bh  = blockIdx.y;
    const int b   = bh >> 3, h = bh & 7;
    const int kv0 = blockIdx.x * 128;
    const int tx = t & 15, ty = t >> 4;
    const int lrow = t >> 2, ld = (t & 3) * 4;

    float acc[4][8];
#pragma unroll
    for (int i = 0; i < 4; i++)
#pragma unroll
        for (int j = 0; j < 8; j++) acc[i][j] = 0.f;

    const float* qbase = g_q + (size_t)b * NL * INNERD + h * DHD;
    const float* kbase = g_k + (size_t)b * KVLEN * INNERD + h * DHD;

    for (int d0 = 0; d0 < DHD; d0 += 16) {
        float4 q4 = *reinterpret_cast<const float4*>(qbase + (size_t)lrow * INNERD + d0 + ld);
        Qs[ld + 0][lrow] = q4.x;
        Qs[ld + 1][lrow] = q4.y;
        Qs[ld + 2][lrow] = q4.z;
        Qs[ld + 3][lrow] = q4.w;
#pragma unroll
        for (int i = 0; i < 2; i++) {
            int kr = kv0 + lrow + 64 * i;
            float4 k4 = make_float4(0.f, 0.f, 0.f, 0.f);
            if (kr < KVLEN)
                k4 = *reinterpret_cast<const float4*>(kbase + (size_t)kr * INNERD + d0 + ld);
            Ks[ld + 0][lrow + 64 * i] = k4.x;
            Ks[ld + 1][lrow + 64 * i] = k4.y;
            Ks[ld + 2][lrow + 64 * i] = k4.z;
            Ks[ld + 3][lrow + 64 * i] = k4.w;
        }
        __syncthreads();
#pragma unroll
        for (int k = 0; k < 16; k++) {
            float qf[4], kf[8];
            *reinterpret_cast<float4*>(&qf[0]) = *reinterpret_cast<const float4*>(&Qs[k][ty * 4]);
            *reinterpret_cast<float4*>(&kf[0]) = *reinterpret_cast<const float4*>(&Ks[k][tx * 8]);
            *reinterpret_cast<float4*>(&kf[4]) = *reinterpret_cast<const float4*>(&Ks[k][tx * 8 + 4]);
#pragma unroll
            for (int i = 0; i < 4; i++)
#pragma unroll
                for (int j = 0; j < 8; j++) acc[i][j] += qf[i] * kf[j];
        }
        __syncthreads();
    }

    const int kvb = kv0 + tx * 8;
    if (kvb < KVLEN) {
        const int mode = g_mask_mode;
        int inval[8];
#pragma unroll
        for (int j = 0; j < 8; j++) {
            int kv = kvb + j;
            inval[j] = (kv < FF) && mask_padded(mask, mode, b * FF + kv);
        }
#pragma unroll
        for (int i = 0; i < 4; i++) {
            int q = ty * 4 + i;
            float* dst = g_sim + ((size_t)bh * NL + q) * KVLEN + kvb;
            float o[8];
#pragma unroll
            for (int j = 0; j < 8; j++) o[j] = inval[j] ? NEGINF : acc[i][j];
            *reinterpret_cast<float4*>(&dst[0]) = *reinterpret_cast<float4*>(&o[0]);
            *reinterpret_cast<float4*>(&dst[4]) = *reinterpret_cast<float4*>(&o[4]);
        }
    }
}

// ---------------- softmax over rows of g_sim, in place ----------------
__global__ void __launch_bounds__(256) softmax_kernel() {
    const int row = blockIdx.x;
    const int t = threadIdx.x;
    float* p = g_sim + (size_t)row * KVLEN;
    const int NV = KVLEN / 4;
    float4 v[9];
    float m = -3.4e38f;
#pragma unroll
    for (int i = 0; i < 9; i++) {
        int idx = t + 256 * i;
        if (idx < NV) {
            v[i] = *(reinterpret_cast<const float4*>(p) + idx);
            m = fmaxf(m, fmaxf(fmaxf(v[i].x, v[i].y), fmaxf(v[i].z, v[i].w)));
        }
    }
    __shared__ float red[8];
    __shared__ float s_max, s_sum;
#pragma unroll
    for (int o = 16; o; o >>= 1) m = fmaxf(m, __shfl_xor_sync(0xffffffffu, m, o));
    if ((t & 31) == 0) red[t >> 5] = m;
    __syncthreads();
    if (t < 8) {
        float a = red[t];
#pragma unroll
        for (int o = 4; o; o >>= 1) a = fmaxf(a, __shfl_xor_sync(0xffu, a, o));
        if (t == 0) s_max = a;
    }
    __syncthreads();
    m = s_max;
    float s = 0.f;
#pragma unroll
    for (int i = 0; i < 9; i++) {
        int idx = t + 256 * i;
        if (idx < NV) {
            v[i].x = __expf(v[i].x - m);
            v[i].y = __expf(v[i].y - m);
            v[i].z = __expf(v[i].z - m);
            v[i].w = __expf(v[i].w - m);
            s += (v[i].x + v[i].y) + (v[i].z + v[i].w);
        }
    }
#pragma unroll
    for (int o = 16; o; o >>= 1) s += __shfl_xor_sync(0xffffffffu, s, o);
    __syncthreads();
    if ((t & 31) == 0) red[t >> 5] = s;
    __syncthreads();
    if (t < 8) {
        float a = red[t];
#pragma unroll
        for (int o = 4; o; o >>= 1) a += __shfl_xor_sync(0xffu, a, o);
        if (t == 0) s_sum = a;
    }
    __syncthreads();
    const float r = 1.0f / s_sum;
#pragma unroll
    for (int i = 0; i < 9; i++) {
        int idx = t + 256 * i;
        if (idx < NV)
            *(reinterpret_cast<float4*>(p) + idx) =
                make_float4(v[i].x * r, v[i].y * r, v[i].z * r, v[i].w * r);
    }
}

// ---------------- attn @ v, split-K into NSPLIT deterministic partials ----------------
__global__ void __launch_bounds__(256) pv_kernel() {
    const int split = blockIdx.x, bh = blockIdx.y;
    const int b = bh >> 3, h = bh & 7;
    const int kvs = split * CHUNK;
    const int kve = min(kvs + CHUNK, KVLEN);
    __shared__ float Ps[16][68];
    __shared__ float Vs[16][68];
    const int t = threadIdx.x;
    const int tx = t & 15, ty = t >> 4;
    const int prow = t >> 2, pk = (t & 3) * 4;
    const int vrow = t >> 4, vd = (t & 15) * 4;
    float acc[4][4];
#pragma unroll
    for (int i = 0; i < 4; i++)
#pragma unroll
        for (int j = 0; j < 4; j++) acc[i][j] = 0.f;

    const float* pbase = g_sim + (size_t)bh * NL * KVLEN;
    const float* vbase = g_v + (size_t)b * KVLEN * INNERD + h * DHD;

    for (int k0 = kvs; k0 < kve; k0 += 16) {
        float4 a4 = *reinterpret_cast<const float4*>(pbase + (size_t)prow * KVLEN + k0 + pk);
        Ps[pk + 0][prow] = a4.x;
        Ps[pk + 1][prow] = a4.y;
        Ps[pk + 2][prow] = a4.z;
        Ps[pk + 3][prow] = a4.w;
        *reinterpret_cast<float4*>(&Vs[vrow][vd]) =
            *reinterpret_cast<const float4*>(vbase + (size_t)(k0 + vrow) * INNERD + vd);
        __syncthreads();
#pragma unroll
        for (int k = 0; k < 16; k++) {
            float pf[4], vf[4];
            *reinterpret_cast<float4*>(&pf[0]) = *reinterpret_cast<const float4*>(&Ps[k][ty * 4]);
            *reinterpret_cast<float4*>(&vf[0]) = *reinterpret_cast<const float4*>(&Vs[k][tx * 4]);
#pragma unroll
            for (int i = 0; i < 4; i++)
#pragma unroll
                for (int j = 0; j < 4; j++) acc[i][j] += pf[i] * vf[j];
        }
        __syncthreads();
    }

    float* obase = g_opart + (size_t)split * (BB * NL * INNERD)
                 + (size_t)(b * NL) * INNERD + h * DHD;
#pragma unroll
    for (int i = 0; i < 4; i++)
        *reinterpret_cast<float4*>(&obase[(size_t)(ty * 4 + i) * INNERD + tx * 4]) =
            make_float4(acc[i][0], acc[i][1], acc[i][2], acc[i][3]);
}

// ---------------- split-K reduction -> bf16 hi/lo operand for out GEMM ----------------
__global__ void __launch_bounds__(256) reduce_kernel() {
    const int i = blockIdx.x * blockDim.x + threadIdx.x;
    float s = 0.f;
#pragma unroll
    for (int k = 0; k < NSPLIT; k++) s += g_opart[(size_t)k * (BB * NL * INNERD) + i];
    __nv_bfloat16 hi = __float2bfloat16(s);
    g_ohi[i] = hi;
    g_olo[i] = __float2bfloat16(s - __bfloat162float(hi));
}

// ---------------- launch ----------------
extern "C" void kernel_launch(void* const* d_in, const int* in_sizes, int n_in,
                              void* d_out, int out_size) {
    const float* x    = (const float*)d_in[0];
    const float* lat  = (const float*)d_in[1];
    const void*  mask = d_in[2];
    const float* gate = (const float*)d_in[3];
    const float* gm   = (const float*)d_in[4];
    const float* bm   = (const float*)d_in[5];
    const float* gl   = (const float*)d_in[6];
    const float* bl   = (const float*)d_in[7];
    const float* Wq   = (const float*)d_in[8];
    const float* Wk   = (const float*)d_in[9];
    const float* Wv   = (const float*)d_in[10];
    const float* Wout = (const float*)d_in[11];
    float* out = (float*)d_out;

    // device-symbol addresses for kernel params
    __nv_bfloat16 *p_ahi, *p_alo, *p_bhi, *p_blo, *p_lathi, *p_latlo;
    __nv_bfloat16 *p_wqhi, *p_wqlo, *p_wohi, *p_wolo, *p_ohi, *p_olo;
    float *p_q, *p_k, *p_v;
    cudaGetSymbolAddress((void**)&p_ahi,   g_ahi);
    cudaGetSymbolAddress((void**)&p_alo,   g_alo);
    cudaGetSymbolAddress((void**)&p_bhi,   g_bhi);
    cudaGetSymbolAddress((void**)&p_blo,   g_blo);
    cudaGetSymbolAddress((void**)&p_lathi, g_lathi);
    cudaGetSymbolAddress((void**)&p_latlo, g_latlo);
    cudaGetSymbolAddress((void**)&p_wqhi,  g_wqhi);
    cudaGetSymbolAddress((void**)&p_wqlo,  g_wqlo);
    cudaGetSymbolAddress((void**)&p_wohi,  g_wohi);
    cudaGetSymbolAddress((void**)&p_wolo,  g_wolo);
    cudaGetSymbolAddress((void**)&p_ohi,   g_ohi);
    cudaGetSymbolAddress((void**)&p_olo,   g_olo);
    cudaGetSymbolAddress((void**)&p_q,     g_q);
    cudaGetSymbolAddress((void**)&p_k,     g_k);
    cudaGetSymbolAddress((void**)&p_v,     g_v);

    cudaFuncSetAttribute(mma_gemm_kernel, cudaFuncAttributeMaxDynamicSharedMemorySize, MMA_SMEM);

    detect_mask_kernel<<<1, 256>>>((const unsigned int*)mask);
    ln_x_kernel<<<BB * FF, 256>>>(x, gm, bm);
    ln_lat_kernel<<<BB * NL, 256>>>(lat, gl, bl, gate);
    // weight transposes + bf16 splits
    wtrans_kernel<<<dim3(DD / 32, INNERD / 32), 256>>>(Wk, p_bhi, p_blo, DD, INNERD);
    wtrans_kernel<<<dim3(DD / 32, INNERD / 32), 256>>>(Wv, p_bhi + INNERD * DD,
                                                       p_blo + INNERD * DD, DD, INNERD);
    wtrans_kernel<<<dim3(DD / 32, INNERD / 32), 256>>>(Wq, p_wqhi, p_wqlo, DD, INNERD);
    wtrans_kernel<<<dim3(INNERD / 32, DD / 32), 256>>>(Wout, p_wohi, p_wolo, INNERD, DD);
    // q = LN(lat) @ Wq * SCALE        (M=512, N=512, K=1024)
    mma_gemm_kernel<<<dim3(INNERD / 128, (BB * NL) / 128), 256, MMA_SMEM>>>(
        p_lathi, p_latlo, p_wqhi, p_wqlo, p_q, DD, INNERD, QSCALE);
    // K = [LN(x); LN(lat)*gate] @ Wk  (M=66048, N=512, K=1024)
    mma_gemm_kernel<<<dim3(INNERD / 128, MROWS / 128), 256, MMA_SMEM>>>(
        p_ahi, p_alo, p_bhi, p_blo, p_k, DD, INNERD, 1.0f);
    // V likewise
    mma_gemm_kernel<<<dim3(INNERD / 128, MROWS / 128), 256, MMA_SMEM>>>(
        p_ahi, p_alo, p_bhi + INNERD * DD, p_blo + INNERD * DD, p_v, DD, INNERD, 1.0f);
    // attention
    sim_kernel<<<dim3((KVLEN + 127) / 128, BB * HH), 256>>>(mask);
    softmax_kernel<<<BB * HH * NL, 256>>>();
    pv_kernel<<<dim3(NSPLIT, BB * HH), 256>>>();
    reduce_kernel<<<(BB * NL * INNERD) / 256, 256>>>();
    // out = o @ Wout                  (M=512, N=1024, K=512)
    mma_gemm_kernel<<<dim3(DD / 128, (BB * NL) / 128), 256, MMA_SMEM>>>(
        p_ohi, p_olo, p_wohi, p_wolo, out, INNERD, DD, 1.0f);
}

// round 15
// speedup vs baseline: 3.0898x; 1.1052x over previous
#include <cuda_runtime.h>
#include <cuda_bf16.h>
#include <math.h>
#include <stdint.h>

// ---------------- problem constants ----------------
#define BB     8
#define FF     8192
#define NL     64
#define DD     1024
#define HH     8
#define DHD    64
#define INNERD 512
#define KVLEN  (FF + NL)        // 8256
#define MROWS  (BB * KVLEN)     // 66048 = 516 * 128
#define NSPLIT 16
#define CHUNK  528
#define QSCALE 0.125f
#define NEGINF -1e30f

// ---------------- scratch (device globals; no allocs allowed) ----------------
__device__ float g_q[BB * NL * INNERD];
__device__ float g_k[MROWS * INNERD];                 // fp32 K (for sim)
__device__ float g_v[MROWS * INNERD];                 // fp32 V (for pv)
__device__ float g_sim[BB * HH * NL * KVLEN];         // raw masked logits
__device__ float g_opart[NSPLIT * BB * NL * INNERD];
__device__ float g_rowm[BB * HH * NL];                // per-row max
__device__ float g_rowrl[BB * HH * NL];               // per-row 1/sumexp
__device__ int   g_mask_mode;
// bf16 split operands
__device__ __align__(16) __nv_bfloat16 g_ahi[(size_t)MROWS * DD];   // KV-rows A hi
__device__ __align__(16) __nv_bfloat16 g_alo[(size_t)MROWS * DD];   // KV-rows A lo
__device__ __align__(16) __nv_bfloat16 g_bhi[2 * INNERD * DD];      // Wk|Wv ^T [N][K]
__device__ __align__(16) __nv_bfloat16 g_blo[2 * INNERD * DD];
__device__ __align__(16) __nv_bfloat16 g_lathi[BB * NL * DD];       // LN(lat) ungated
__device__ __align__(16) __nv_bfloat16 g_latlo[BB * NL * DD];
__device__ __align__(16) __nv_bfloat16 g_wqhi[INNERD * DD];         // Wq^T [512][1024]
__device__ __align__(16) __nv_bfloat16 g_wqlo[INNERD * DD];
__device__ __align__(16) __nv_bfloat16 g_wohi[DD * INNERD];         // Wout^T [1024][512]
__device__ __align__(16) __nv_bfloat16 g_wolo[DD * INNERD];
__device__ __align__(16) __nv_bfloat16 g_ohi[BB * NL * INNERD];     // attn@v hi/lo
__device__ __align__(16) __nv_bfloat16 g_olo[BB * NL * INNERD];

// ================= low-level helpers (sm_80-era only) ==========
__device__ __forceinline__ uint32_t smem_to_u32(const void* p) {
    uint32_t a;
    asm("{ .reg .u64 t; cvta.to.shared.u64 t, %1; cvt.u32.u64 %0, t; }" : "=r"(a) : "l"(p));
    return a;
}
__device__ __forceinline__ void cp16(uint32_t s, const void* g) {
    asm volatile("cp.async.cg.shared.global [%0], [%1], 16;" :: "r"(s), "l"(g));
}
#define CP_COMMIT() asm volatile("cp.async.commit_group;" ::: "memory")
#define CP_WAIT1()  asm volatile("cp.async.wait_group 1;" ::: "memory")
#define CP_WAIT0()  asm volatile("cp.async.wait_group 0;" ::: "memory")
__device__ __forceinline__ void ldsm_x4(uint32_t* r, uint32_t addr) {
    asm volatile("ldmatrix.sync.aligned.m8n8.x4.shared.b16 {%0,%1,%2,%3}, [%4];"
                 : "=r"(r[0]), "=r"(r[1]), "=r"(r[2]), "=r"(r[3]) : "r"(addr));
}
__device__ __forceinline__ void mma_bf16(float* c, const uint32_t* a, const uint32_t* b) {
    asm volatile("mma.sync.aligned.m16n8k16.row.col.f32.bf16.bf16.f32 "
                 "{%0,%1,%2,%3}, {%4,%5,%6,%7}, {%8,%9}, {%0,%1,%2,%3};"
                 : "+f"(c[0]), "+f"(c[1]), "+f"(c[2]), "+f"(c[3])
                 : "r"(a[0]), "r"(a[1]), "r"(a[2]), "r"(a[3]), "r"(b[0]), "r"(b[1]));
}
__device__ __forceinline__ uint32_t pack_bf2(float a, float b) {
    __nv_bfloat162 t = __floats2bfloat162_rn(a, b);
    return *reinterpret_cast<uint32_t*>(&t);
}

// ---------------- mask dtype detection (proven) ----------------
__global__ void detect_mask_kernel(const unsigned int* __restrict__ mw) {
    __shared__ unsigned int sh[2];
    if (threadIdx.x == 0) { sh[0] = 0u; sh[1] = 0u; }
    __syncthreads();
    unsigned int a1 = 0u, a3 = 0u;
    for (int i = threadIdx.x; i < 16384; i += 256) {
        unsigned int w = mw[i];
        a1 |= (w & 0x0000FF00u);
        a3 |= (w & 0xFF000000u);
    }
#pragma unroll
    for (int o = 16; o; o >>= 1) {
        a1 |= __shfl_xor_sync(0xffffffffu, a1, o);
        a3 |= __shfl_xor_sync(0xffffffffu, a3, o);
    }
    if ((threadIdx.x & 31) == 0) { atomicOr(&sh[0], a1); atomicOr(&sh[1], a3); }
    __syncthreads();
    if (threadIdx.x == 0) g_mask_mode = sh[0] ? 0 : (sh[1] ? 2 : 1);
}
__device__ __forceinline__ int mask_padded(const void* mask, int mode, int idx) {
    if (mode == 0) return ((const unsigned char*)mask)[idx] != 0;
    if (mode == 1) return ((const int*)mask)[idx] != 0;
    return ((const float*)mask)[idx] != 0.0f;
}

// ---------------- LN core ----------
__device__ __forceinline__ float4 ln_row(const float* __restrict__ in,
                                         const float* __restrict__ gamma,
                                         const float* __restrict__ beta, int row, int t) {
    float4 v = reinterpret_cast<const float4*>(in + (size_t)row * DD)[t];
    float s  = (v.x + v.y) + (v.z + v.w);
    float ss = v.x * v.x + v.y * v.y + v.z * v.z + v.w * v.w;
    __shared__ float red[16];
    __shared__ float s_mu, s_rstd;
#pragma unroll
    for (int o = 16; o; o >>= 1) {
        s  += __shfl_xor_sync(0xffffffffu, s, o);
        ss += __shfl_xor_sync(0xffffffffu, ss, o);
    }
    if ((t & 31) == 0) { red[t >> 5] = s; red[(t >> 5) + 8] = ss; }
    __syncthreads();
    if (t < 8) {
        float a = red[t], b2 = red[t + 8];
#pragma unroll
        for (int o = 4; o; o >>= 1) {
            a  += __shfl_xor_sync(0xffu, a, o);
            b2 += __shfl_xor_sync(0xffu, b2, o);
        }
        if (t == 0) {
            float mu = a * (1.0f / DD);
            float var = b2 * (1.0f / DD) - mu * mu;
            s_mu = mu; s_rstd = rsqrtf(var + 1e-5f);
        }
    }
    __syncthreads();
    const float mu = s_mu, rstd = s_rstd;
    float4 g4 = reinterpret_cast<const float4*>(gamma)[t];
    float4 b4 = reinterpret_cast<const float4*>(beta)[t];
    float4 o4;
    o4.x = (v.x - mu) * rstd * g4.x + b4.x;
    o4.y = (v.y - mu) * rstd * g4.y + b4.y;
    o4.z = (v.z - mu) * rstd * g4.z + b4.z;
    o4.w = (v.w - mu) * rstd * g4.w + b4.w;
    return o4;
}

__device__ __forceinline__ void write_hilo_to(__nv_bfloat16* hp, __nv_bfloat16* lp,
                                              size_t elem, float a, float b, float c, float d) {
    float hf0 = __bfloat162float(__float2bfloat16(a));
    float hf1 = __bfloat162float(__float2bfloat16(b));
    float hf2 = __bfloat162float(__float2bfloat16(c));
    float hf3 = __bfloat162float(__float2bfloat16(d));
    uint2 hw = make_uint2(pack_bf2(hf0, hf1), pack_bf2(hf2, hf3));
    uint2 lw = make_uint2(pack_bf2(a - hf0, b - hf1), pack_bf2(c - hf2, d - hf3));
    *reinterpret_cast<uint2*>(hp + elem) = hw;
    *reinterpret_cast<uint2*>(lp + elem) = lw;
}

// LN for x: bf16 hi/lo into KV-row layout
__global__ void __launch_bounds__(256) ln_x_kernel(const float* __restrict__ in,
                                                   const float* __restrict__ gamma,
                                                   const float* __restrict__ beta) {
    const int row = blockIdx.x;
    const int t = threadIdx.x;
    float4 o4 = ln_row(in, gamma, beta, row, t);
    const int b = row / FF, s = row - b * FF;
    const size_t kvrow = (size_t)b * KVLEN + s;
    write_hilo_to(g_ahi, g_alo, kvrow * DD + t * 4, o4.x, o4.y, o4.z, o4.w);
}

// LN for latents: ungated hi/lo (q GEMM A) + gated hi/lo KV rows
__global__ void __launch_bounds__(256) ln_lat_kernel(const float* __restrict__ in,
                                                     const float* __restrict__ gamma,
                                                     const float* __restrict__ beta,
                                                     const float* __restrict__ gate_p) {
    const int row = blockIdx.x;               // 0 .. BB*NL-1
    const int t = threadIdx.x;
    float4 o4 = ln_row(in, gamma, beta, row, t);
    write_hilo_to(g_lathi, g_latlo, (size_t)row * DD + t * 4, o4.x, o4.y, o4.z, o4.w);
    const float g = *gate_p;
    const int b = row / NL, l = row - b * NL;
    const size_t kvrow = (size_t)b * KVLEN + FF + l;
    write_hilo_to(g_ahi, g_alo, kvrow * DD + t * 4, o4.x * g, o4.y * g, o4.z * g, o4.w * g);
}

// ---------------- W transpose + bf16 split: [Kdim][Ndim] fp32 -> [Ndim][Kdim] hi/lo ------
__global__ void __launch_bounds__(256) wtrans_kernel(const float* __restrict__ W,
                                                     __nv_bfloat16* __restrict__ dhi,
                                                     __nv_bfloat16* __restrict__ dlo,
                                                     int Kdim, int Ndim) {
    __shared__ float tbuf[32][33];
    const int k0 = blockIdx.x * 32, n0 = blockIdx.y * 32;
    const int tx = threadIdx.x & 31, ty = threadIdx.x >> 5;   // 32 x 8
#pragma unroll
    for (int i = 0; i < 4; i++)
        tbuf[ty + 8 * i][tx] = W[(size_t)(k0 + ty + 8 * i) * Ndim + n0 + tx];
    __syncthreads();
#pragma unroll
    for (int i = 0; i < 4; i++) {
        const int n = n0 + ty + 8 * i, k = k0 + tx;
        float v = tbuf[tx][ty + 8 * i];
        __nv_bfloat16 hi = __float2bfloat16(v);
        float lo = v - __bfloat162float(hi);
        const size_t idx = (size_t)n * Kdim + k;
        dhi[idx] = hi;
        dlo[idx] = __float2bfloat16(lo);
    }
}

// ================= generic bf16-split MMA GEMM =================
// C[M x N] = alpha * A[M x K] @ B[N x K]^T   (A,B as hi/lo bf16; 3-term split, fp32 acc)
// Tile 128x128, BK=32, 2-stage cp.async (80KB smem -> 2 CTAs/SM), 8 warps (2m x 4n).
#define BKK    32
#define APAD   40                    // 80B row stride: conflict-free ldmatrix
#define KVTILE (128 * APAD)          // bf16 elems per array per stage
#define MMA_SMEM (8 * KVTILE * 2)    // 2 stages x 4 arrays = 81920 B

__device__ __forceinline__ void issue_tiles(uint32_t sbase, int buf,
                                            const __nv_bfloat16* __restrict__ Ah,
                                            const __nv_bfloat16* __restrict__ Al,
                                            const __nv_bfloat16* __restrict__ Bh,
                                            const __nv_bfloat16* __restrict__ Bl,
                                            int m0, int n0, int k0, int strideK, int tid) {
#pragma unroll
    for (int arr = 0; arr < 4; arr++) {
        const __nv_bfloat16* src = (arr == 0) ? Ah : (arr == 1) ? Al : (arr == 2) ? Bh : Bl;
        const int rbase = (arr < 2) ? m0 : n0;
#pragma unroll
        for (int i = 0; i < 2; i++) {
            int id = tid + 256 * i;                 // 0..511
            int row = id >> 2, c4 = id & 3;
            const __nv_bfloat16* gp = src + (size_t)(rbase + row) * strideK + k0 + c4 * 8;
            uint32_t sp = sbase + ((buf * 4 + arr) * KVTILE + row * APAD + c4 * 8) * 2;
            cp16(sp, gp);
        }
    }
}

__device__ __forceinline__ void compute_chunk(uint32_t sbase, int buf,
                                              int warp_m, int warp_n, int lane,
                                              float (&acc)[4][4][4]) {
    const uint32_t ab = sbase + ((buf * 4 + 0) * KVTILE) * 2;
    const uint32_t lb = sbase + ((buf * 4 + 1) * KVTILE) * 2;
    const uint32_t bb = sbase + ((buf * 4 + 2) * KVTILE) * 2;
    const uint32_t vb = sbase + ((buf * 4 + 3) * KVTILE) * 2;
#pragma unroll
    for (int ks = 0; ks < 2; ks++) {
        const int koff = ks * 16;
        uint32_t ah[4][4], al[4][4];
#pragma unroll
        for (int mt = 0; mt < 4; mt++) {
            const uint32_t ro = ((warp_m * 64 + mt * 16 + (lane & 15)) * APAD
                                 + koff + (lane >> 4) * 8) * 2;
            ldsm_x4(ah[mt], ab + ro);
            ldsm_x4(al[mt], lb + ro);
        }
        uint32_t bh[4][2], bl[4][2];
#pragma unroll
        for (int p = 0; p < 2; p++) {
            const int g2 = lane >> 3;               // 0..3
            const uint32_t ro = ((warp_n * 32 + p * 16 + (g2 >> 1) * 8 + (lane & 7)) * APAD
                                 + koff + (g2 & 1) * 8) * 2;
            uint32_t r[4];
            ldsm_x4(r, bb + ro);
            bh[2 * p][0] = r[0]; bh[2 * p][1] = r[1];
            bh[2 * p + 1][0] = r[2]; bh[2 * p + 1][1] = r[3];
            ldsm_x4(r, vb + ro);
            bl[2 * p][0] = r[0]; bl[2 * p][1] = r[1];
            bl[2 * p + 1][0] = r[2]; bl[2 * p + 1][1] = r[3];
        }
        // term-major ordering: same-acc RAW 16 MMAs apart
#pragma unroll
        for (int mt = 0; mt < 4; mt++)
#pragma unroll
            for (int nt = 0; nt < 4; nt++) mma_bf16(acc[mt][nt], ah[mt], bh[nt]);
#pragma unroll
        for (int mt = 0; mt < 4; mt++)
#pragma unroll
            for (int nt = 0; nt < 4; nt++) mma_bf16(acc[mt][nt], ah[mt], bl[nt]);
#pragma unroll
        for (int mt = 0; mt < 4; mt++)
#pragma unroll
            for (int nt = 0; nt < 4; nt++) mma_bf16(acc[mt][nt], al[mt], bh[nt]);
    }
}

__global__ void __launch_bounds__(256, 2) mma_gemm_kernel(
    const __nv_bfloat16* __restrict__ Ah, const __nv_bfloat16* __restrict__ Al,
    const __nv_bfloat16* __restrict__ Bh, const __nv_bfloat16* __restrict__ Bl,
    float* __restrict__ C, int K, int ldc, float alpha) {
    extern __shared__ __nv_bfloat16 sm[];
    const uint32_t sbase = smem_to_u32(sm);
    const int tid = threadIdx.x;
    const int lane = tid & 31, wid = tid >> 5;
    const int warp_m = wid >> 2, warp_n = wid & 3;
    const int m0 = blockIdx.y * 128, n0 = blockIdx.x * 128;

    float acc[4][4][4];
#pragma unroll
    for (int i = 0; i < 4; i++)
#pragma unroll
        for (int j = 0; j < 4; j++)
#pragma unroll
            for (int q = 0; q < 4; q++) acc[i][j][q] = 0.f;

    const int NITER = K / BKK;
    issue_tiles(sbase, 0, Ah, Al, Bh, Bl, m0, n0, 0, K, tid);
    CP_COMMIT();

    for (int c = 0; c < NITER; c++) {
        const int buf = c & 1;
        if (c < NITER - 1) {
            issue_tiles(sbase, buf ^ 1, Ah, Al, Bh, Bl, m0, n0, (c + 1) * BKK, K, tid);
            CP_COMMIT();
            CP_WAIT1();
        } else {
            CP_WAIT0();
        }
        __syncthreads();
        compute_chunk(sbase, buf, warp_m, warp_n, lane, acc);
        __syncthreads();
    }

#pragma unroll
    for (int mt = 0; mt < 4; mt++) {
        const int r0 = m0 + warp_m * 64 + mt * 16 + (lane >> 2);
#pragma unroll
        for (int nt = 0; nt < 4; nt++) {
            const int cc = n0 + warp_n * 32 + nt * 8 + (lane & 3) * 2;
            *reinterpret_cast<float2*>(&C[(size_t)r0 * ldc + cc]) =
                make_float2(acc[mt][nt][0] * alpha, acc[mt][nt][1] * alpha);
            *reinterpret_cast<float2*>(&C[(size_t)(r0 + 8) * ldc + cc]) =
                make_float2(acc[mt][nt][2] * alpha, acc[mt][nt][3] * alpha);
        }
    }
}

// ---------------- sim = (q*SCALE) @ k^T per (b,h), fused padding mask ----------------
__global__ void __launch_bounds__(256) sim_kernel(const void* __restrict__ mask) {
    __shared__ float Qs[16][64];
    __shared__ float Ks[16][132];
    const int t   = threadIdx.x;
    const int bh  = blockIdx.y;
    const int b   = bh >> 3, h = bh & 7;
    const int kv0 = blockIdx.x * 128;
    const int tx = t & 15, ty = t >> 4;
    const int lrow = t >> 2, ld = (t & 3) * 4;

    float acc[4][8];
#pragma unroll
    for (int i = 0; i < 4; i++)
#pragma unroll
        for (int j = 0; j < 8; j++) acc[i][j] = 0.f;

    const float* qbase = g_q + (size_t)b * NL * INNERD + h * DHD;
    const float* kbase = g_k + (size_t)b * KVLEN * INNERD + h * DHD;

    for (int d0 = 0; d0 < DHD; d0 += 16) {
        float4 q4 = *reinterpret_cast<const float4*>(qbase + (size_t)lrow * INNERD + d0 + ld);
        Qs[ld + 0][lrow] = q4.x;
        Qs[ld + 1][lrow] = q4.y;
        Qs[ld + 2][lrow] = q4.z;
        Qs[ld + 3][lrow] = q4.w;
#pragma unroll
        for (int i = 0; i < 2; i++) {
            int kr = kv0 + lrow + 64 * i;
            float4 k4 = make_float4(0.f, 0.f, 0.f, 0.f);
            if (kr < KVLEN)
                k4 = *reinterpret_cast<const float4*>(kbase + (size_t)kr * INNERD + d0 + ld);
            Ks[ld + 0][lrow + 64 * i] = k4.x;
            Ks[ld + 1][lrow + 64 * i] = k4.y;
            Ks[ld + 2][lrow + 64 * i] = k4.z;
            Ks[ld + 3][lrow + 64 * i] = k4.w;
        }
        __syncthreads();
#pragma unroll
        for (int k = 0; k < 16; k++) {
            float qf[4], kf[8];
            *reinterpret_cast<float4*>(&qf[0]) = *reinterpret_cast<const float4*>(&Qs[k][ty * 4]);
            *reinterpret_cast<float4*>(&kf[0]) = *reinterpret_cast<const float4*>(&Ks[k][tx * 8]);
            *reinterpret_cast<float4*>(&kf[4]) = *reinterpret_cast<const float4*>(&Ks[k][tx * 8 + 4]);
#pragma unroll
            for (int i = 0; i < 4; i++)
#pragma unroll
                for (int j = 0; j < 8; j++) acc[i][j] += qf[i] * kf[j];
        }
        __syncthreads();
    }

    const int kvb = kv0 + tx * 8;
    if (kvb < KVLEN) {
        const int mode = g_mask_mode;
        int inval[8];
#pragma unroll
        for (int j = 0; j < 8; j++) {
            int kv = kvb + j;
            inval[j] = (kv < FF) && mask_padded(mask, mode, b * FF + kv);
        }
#pragma unroll
        for (int i = 0; i < 4; i++) {
            int q = ty * 4 + i;
            float* dst = g_sim + ((size_t)bh * NL + q) * KVLEN + kvb;
            float o[8];
#pragma unroll
            for (int j = 0; j < 8; j++) o[j] = inval[j] ? NEGINF : acc[i][j];
            *reinterpret_cast<float4*>(&dst[0]) = *reinterpret_cast<float4*>(&o[0]);
            *reinterpret_cast<float4*>(&dst[4]) = *reinterpret_cast<float4*>(&o[4]);
        }
    }
}

// ---------------- rowstat: per-row max + 1/sumexp (replaces softmax pass) ----------------
__global__ void __launch_bounds__(256) rowstat_kernel() {
    const int row = blockIdx.x;
    const int t = threadIdx.x;
    const float4* p = reinterpret_cast<const float4*>(g_sim + (size_t)row * KVLEN);
    const int NV = KVLEN / 4;   // 2064
    __shared__ float red[8];
    __shared__ float s_max, s_sum;

    float m = -3.4e38f;
    for (int idx = t; idx < NV; idx += 256) {
        float4 v = p[idx];
        m = fmaxf(m, fmaxf(fmaxf(v.x, v.y), fmaxf(v.z, v.w)));
    }
#pragma unroll
    for (int o = 16; o; o >>= 1) m = fmaxf(m, __shfl_xor_sync(0xffffffffu, m, o));
    if ((t & 31) == 0) red[t >> 5] = m;
    __syncthreads();
    if (t < 8) {
        float a = red[t];
#pragma unroll
        for (int o = 4; o; o >>= 1) a = fmaxf(a, __shfl_xor_sync(0xffu, a, o));
        if (t == 0) s_max = a;
    }
    __syncthreads();
    m = s_max;
    float s = 0.f;
    for (int idx = t; idx < NV; idx += 256) {   // second pass: L2 hits
        float4 v = p[idx];
        s += __expf(v.x - m) + __expf(v.y - m) + __expf(v.z - m) + __expf(v.w - m);
    }
#pragma unroll
    for (int o = 16; o; o >>= 1) s += __shfl_xor_sync(0xffffffffu, s, o);
    __syncthreads();
    if ((t & 31) == 0) red[t >> 5] = s;
    __syncthreads();
    if (t < 8) {
        float a = red[t];
#pragma unroll
        for (int o = 4; o; o >>= 1) a += __shfl_xor_sync(0xffu, a, o);
        if (t == 0) s_sum = a;
    }
    __syncthreads();
    if (t == 0) { g_rowm[row] = m; g_rowrl[row] = 1.0f / s_sum; }
}

// ---------------- attn @ v with in-loop softmax normalization, split-K partials ----------
__global__ void __launch_bounds__(256) pv_kernel() {
    const int split = blockIdx.x, bh = blockIdx.y;
    const int b = bh >> 3, h = bh & 7;
    const int kvs = split * CHUNK;
    const int kve = min(kvs + CHUNK, KVLEN);
    __shared__ float Ps[16][68];
    __shared__ float Vs[16][68];
    const int t = threadIdx.x;
    const int tx = t & 15, ty = t >> 4;
    const int prow = t >> 2, pk = (t & 3) * 4;
    const int vrow = t >> 4, vd = (t & 15) * 4;
    float acc[4][4];
#pragma unroll
    for (int i = 0; i < 4; i++)
#pragma unroll
        for (int j = 0; j < 4; j++) acc[i][j] = 0.f;

    const float* pbase = g_sim + (size_t)bh * NL * KVLEN;
    const float* vbase = g_v + (size_t)b * KVLEN * INNERD + h * DHD;
    const float rm = g_rowm[bh * NL + prow];
    const float rl = g_rowrl[bh * NL + prow];

    for (int k0 = kvs; k0 < kve; k0 += 16) {
        float4 a4 = *reinterpret_cast<const float4*>(pbase + (size_t)prow * KVLEN + k0 + pk);
        // p = exp(s - m) / l ; masked lanes (s = -1e30) underflow to exactly 0
        Ps[pk + 0][prow] = __expf(a4.x - rm) * rl;
        Ps[pk + 1][prow] = __expf(a4.y - rm) * rl;
        Ps[pk + 2][prow] = __expf(a4.z - rm) * rl;
        Ps[pk + 3][prow] = __expf(a4.w - rm) * rl;
        *reinterpret_cast<float4*>(&Vs[vrow][vd]) =
            *reinterpret_cast<const float4*>(vbase + (size_t)(k0 + vrow) * INNERD + vd);
        __syncthreads();
#pragma unroll
        for (int k = 0; k < 16; k++) {
            float pf[4], vf[4];
            *reinterpret_cast<float4*>(&pf[0]) = *reinterpret_cast<const float4*>(&Ps[k][ty * 4]);
            *reinterpret_cast<float4*>(&vf[0]) = *reinterpret_cast<const float4*>(&Vs[k][tx * 4]);
#pragma unroll
            for (int i = 0; i < 4; i++)
#pragma unroll
                for (int j = 0; j < 4; j++) acc[i][j] += pf[i] * vf[j];
        }
        __syncthreads();
    }

    float* obase = g_opart + (size_t)split * (BB * NL * INNERD)
                 + (size_t)(b * NL) * INNERD + h * DHD;
#pragma unroll
    for (int i = 0; i < 4; i++)
        *reinterpret_cast<float4*>(&obase[(size_t)(ty * 4 + i) * INNERD + tx * 4]) =
            make_float4(acc[i][0], acc[i][1], acc[i][2], acc[i][3]);
}

// ---------------- split-K reduction -> bf16 hi/lo operand for out GEMM ----------------
__global__ void __launch_bounds__(256) reduce_kernel() {
    const int i = blockIdx.x * blockDim.x + threadIdx.x;
    float s = 0.f;
#pragma unroll
    for (int k = 0; k < NSPLIT; k++) s += g_opart[(size_t)k * (BB * NL * INNERD) + i];
    __nv_bfloat16 hi = __float2bfloat16(s);
    g_ohi[i] = hi;
    g_olo[i] = __float2bfloat16(s - __bfloat162float(hi));
}

// ---------------- launch ----------------
extern "C" void kernel_launch(void* const* d_in, const int* in_sizes, int n_in,
                              void* d_out, int out_size) {
    const float* x    = (const float*)d_in[0];
    const float* lat  = (const float*)d_in[1];
    const void*  mask = d_in[2];
    const float* gate = (const float*)d_in[3];
    const float* gm   = (const float*)d_in[4];
    const float* bm   = (const float*)d_in[5];
    const float* gl   = (const float*)d_in[6];
    const float* bl   = (const float*)d_in[7];
    const float* Wq   = (const float*)d_in[8];
    const float* Wk   = (const float*)d_in[9];
    const float* Wv   = (const float*)d_in[10];
    const float* Wout = (const float*)d_in[11];
    float* out = (float*)d_out;

    __nv_bfloat16 *p_ahi, *p_alo, *p_bhi, *p_blo, *p_lathi, *p_latlo;
    __nv_bfloat16 *p_wqhi, *p_wqlo, *p_wohi, *p_wolo, *p_ohi, *p_olo;
    float *p_q, *p_k, *p_v;
    cudaGetSymbolAddress((void**)&p_ahi,   g_ahi);
    cudaGetSymbolAddress((void**)&p_alo,   g_alo);
    cudaGetSymbolAddress((void**)&p_bhi,   g_bhi);
    cudaGetSymbolAddress((void**)&p_blo,   g_blo);
    cudaGetSymbolAddress((void**)&p_lathi, g_lathi);
    cudaGetSymbolAddress((void**)&p_latlo, g_latlo);
    cudaGetSymbolAddress((void**)&p_wqhi,  g_wqhi);
    cudaGetSymbolAddress((void**)&p_wqlo,  g_wqlo);
    cudaGetSymbolAddress((void**)&p_wohi,  g_wohi);
    cudaGetSymbolAddress((void**)&p_wolo,  g_wolo);
    cudaGetSymbolAddress((void**)&p_ohi,   g_ohi);
    cudaGetSymbolAddress((void**)&p_olo,   g_olo);
    cudaGetSymbolAddress((void**)&p_q,     g_q);
    cudaGetSymbolAddress((void**)&p_k,     g_k);
    cudaGetSymbolAddress((void**)&p_v,     g_v);

    cudaFuncSetAttribute(mma_gemm_kernel, cudaFuncAttributeMaxDynamicSharedMemorySize, MMA_SMEM);

    detect_mask_kernel<<<1, 256>>>((const unsigned int*)mask);
    ln_x_kernel<<<BB * FF, 256>>>(x, gm, bm);
    ln_lat_kernel<<<BB * NL, 256>>>(lat, gl, bl, gate);
    // weight transposes + bf16 splits
    wtrans_kernel<<<dim3(DD / 32, INNERD / 32), 256>>>(Wk, p_bhi, p_blo, DD, INNERD);
    wtrans_kernel<<<dim3(DD / 32, INNERD / 32), 256>>>(Wv, p_bhi + INNERD * DD,
                                                       p_blo + INNERD * DD, DD, INNERD);
    wtrans_kernel<<<dim3(DD / 32, INNERD / 32), 256>>>(Wq, p_wqhi, p_wqlo, DD, INNERD);
    wtrans_kernel<<<dim3(INNERD / 32, DD / 32), 256>>>(Wout, p_wohi, p_wolo, INNERD, DD);
    // q = LN(lat) @ Wq * SCALE        (M=512, N=512, K=1024)
    mma_gemm_kernel<<<dim3(INNERD / 128, (BB * NL) / 128), 256, MMA_SMEM>>>(
        p_lathi, p_latlo, p_wqhi, p_wqlo, p_q, DD, INNERD, QSCALE);
    // K = [LN(x); LN(lat)*gate] @ Wk  (M=66048, N=512, K=1024)
    mma_gemm_kernel<<<dim3(INNERD / 128, MROWS / 128), 256, MMA_SMEM>>>(
        p_ahi, p_alo, p_bhi, p_blo, p_k, DD, INNERD, 1.0f);
    // V likewise
    mma_gemm_kernel<<<dim3(INNERD / 128, MROWS / 128), 256, MMA_SMEM>>>(
        p_ahi, p_alo, p_bhi + INNERD * DD, p_blo + INNERD * DD, p_v, DD, INNERD, 1.0f);
    // attention: raw logits -> row stats -> normalized pv
    sim_kernel<<<dim3((KVLEN + 127) / 128, BB * HH), 256>>>(mask);
    rowstat_kernel<<<BB * HH * NL, 256>>>();
    pv_kernel<<<dim3(NSPLIT, BB * HH), 256>>>();
    reduce_kernel<<<(BB * NL * INNERD) / 256, 256>>>();
    // out = o @ Wout                  (M=512, N=1024, K=512)
    mma_gemm_kernel<<<dim3(DD / 128, (BB * NL) / 128), 256, MMA_SMEM>>>(
        p_ohi, p_olo, p_wohi, p_wolo, out, INNERD, DD, 1.0f);
}

// round 16
// speedup vs baseline: 3.2475x; 1.0510x over previous
#include <cuda_runtime.h>
#include <cuda_bf16.h>
#include <math.h>
#include <stdint.h>

// ---------------- problem constants ----------------
#define BB     8
#define FF     8192
#define NL     64
#define DD     1024
#define HH     8
#define DHD    64
#define INNERD 512
#define KVLEN  (FF + NL)        // 8256
#define MROWS  (BB * KVLEN)     // 66048 = 516 * 128
#define NSPLIT 16
#define CHUNK  528
#define QSCALE 0.125f
#define NEGINF -1e30f

// ---------------- scratch (device globals; no allocs allowed) ----------------
__device__ float g_v[MROWS * INNERD];                 // fp32 V (for pv)
__device__ float g_sim[BB * HH * NL * KVLEN];         // raw masked logits
__device__ float g_opart[NSPLIT * BB * NL * INNERD];
__device__ float g_rowm[BB * HH * NL];                // per-row max
__device__ float g_rowrl[BB * HH * NL];               // per-row 1/sumexp
__device__ int   g_mask_mode;
// bf16 split operands
__device__ __align__(16) __nv_bfloat16 g_ahi[(size_t)MROWS * DD];   // KV-rows A hi
__device__ __align__(16) __nv_bfloat16 g_alo[(size_t)MROWS * DD];   // KV-rows A lo
__device__ __align__(16) __nv_bfloat16 g_bhi[2 * INNERD * DD];      // Wk|Wv ^T [N][K]
__device__ __align__(16) __nv_bfloat16 g_blo[2 * INNERD * DD];
__device__ __align__(16) __nv_bfloat16 g_lathi[BB * NL * DD];       // LN(lat) ungated
__device__ __align__(16) __nv_bfloat16 g_latlo[BB * NL * DD];
__device__ __align__(16) __nv_bfloat16 g_wqhi[INNERD * DD];         // Wq^T [512][1024]
__device__ __align__(16) __nv_bfloat16 g_wqlo[INNERD * DD];
__device__ __align__(16) __nv_bfloat16 g_wohi[DD * INNERD];         // Wout^T [1024][512]
__device__ __align__(16) __nv_bfloat16 g_wolo[DD * INNERD];
__device__ __align__(16) __nv_bfloat16 g_ohi[BB * NL * INNERD];     // attn@v hi/lo
__device__ __align__(16) __nv_bfloat16 g_olo[BB * NL * INNERD];
__device__ __align__(16) __nv_bfloat16 g_qhi[BB * NL * INNERD];     // q*SCALE hi/lo
__device__ __align__(16) __nv_bfloat16 g_qlo[BB * NL * INNERD];
__device__ __align__(16) __nv_bfloat16 g_khi[(size_t)MROWS * INNERD]; // K hi/lo
__device__ __align__(16) __nv_bfloat16 g_klo[(size_t)MROWS * INNERD];

// ================= low-level helpers (sm_80-era only) ==========
__device__ __forceinline__ uint32_t smem_to_u32(const void* p) {
    uint32_t a;
    asm("{ .reg .u64 t; cvta.to.shared.u64 t, %1; cvt.u32.u64 %0, t; }" : "=r"(a) : "l"(p));
    return a;
}
__device__ __forceinline__ void cp16(uint32_t s, const void* g) {
    asm volatile("cp.async.cg.shared.global [%0], [%1], 16;" :: "r"(s), "l"(g));
}
__device__ __forceinline__ void cp16z(uint32_t s, const void* g, int pred) {
    asm volatile("cp.async.cg.shared.global [%0], [%1], 16, %2;"
                 :: "r"(s), "l"(g), "r"(pred ? 16 : 0));
}
#define CP_COMMIT() asm volatile("cp.async.commit_group;" ::: "memory")
#define CP_WAIT1()  asm volatile("cp.async.wait_group 1;" ::: "memory")
#define CP_WAIT0()  asm volatile("cp.async.wait_group 0;" ::: "memory")
__device__ __forceinline__ void ldsm_x4(uint32_t* r, uint32_t addr) {
    asm volatile("ldmatrix.sync.aligned.m8n8.x4.shared.b16 {%0,%1,%2,%3}, [%4];"
                 : "=r"(r[0]), "=r"(r[1]), "=r"(r[2]), "=r"(r[3]) : "r"(addr));
}
__device__ __forceinline__ void mma_bf16(float* c, const uint32_t* a, const uint32_t* b) {
    asm volatile("mma.sync.aligned.m16n8k16.row.col.f32.bf16.bf16.f32 "
                 "{%0,%1,%2,%3}, {%4,%5,%6,%7}, {%8,%9}, {%0,%1,%2,%3};"
                 : "+f"(c[0]), "+f"(c[1]), "+f"(c[2]), "+f"(c[3])
                 : "r"(a[0]), "r"(a[1]), "r"(a[2]), "r"(a[3]), "r"(b[0]), "r"(b[1]));
}
__device__ __forceinline__ uint32_t pack_bf2(float a, float b) {
    __nv_bfloat162 t = __floats2bfloat162_rn(a, b);
    return *reinterpret_cast<uint32_t*>(&t);
}

// fast exp: FFMA-pipe only (no MUFU). rel err ~2.4e-6; x <= ~-87 -> ~0 (2^-126 * p).
__device__ __forceinline__ float fast_exp(float x) {
    float t = x * 1.4426950408889634f;            // x * log2(e)
    t = fminf(fmaxf(t, -126.0f), 126.0f);
    float fr = t + 12582912.0f;                    // round-to-nearest-int (magic)
    int   n  = __float_as_int(fr) - 0x4B400000;    // integer part
    float f  = t - (fr - 12582912.0f);             // frac in [-0.5, 0.5]
    float u  = f * 0.6931471805599453f;            // 2^f = e^u, |u| <= 0.347
    float p  = 8.3333333e-3f;                      // 1/120
    p = fmaf(p, u, 4.1666667e-2f);                 // 1/24
    p = fmaf(p, u, 1.6666667e-1f);                 // 1/6
    p = fmaf(p, u, 0.5f);
    p = fmaf(p, u, 1.0f);
    p = fmaf(p, u, 1.0f);
    return __int_as_float((n + 127) << 23) * p;
}

// ---------------- mask dtype detection (proven) ----------------
__global__ void detect_mask_kernel(const unsigned int* __restrict__ mw) {
    __shared__ unsigned int sh[2];
    if (threadIdx.x == 0) { sh[0] = 0u; sh[1] = 0u; }
    __syncthreads();
    unsigned int a1 = 0u, a3 = 0u;
    for (int i = threadIdx.x; i < 16384; i += 256) {
        unsigned int w = mw[i];
        a1 |= (w & 0x0000FF00u);
        a3 |= (w & 0xFF000000u);
    }
#pragma unroll
    for (int o = 16; o; o >>= 1) {
        a1 |= __shfl_xor_sync(0xffffffffu, a1, o);
        a3 |= __shfl_xor_sync(0xffffffffu, a3, o);
    }
    if ((threadIdx.x & 31) == 0) { atomicOr(&sh[0], a1); atomicOr(&sh[1], a3); }
    __syncthreads();
    if (threadIdx.x == 0) g_mask_mode = sh[0] ? 0 : (sh[1] ? 2 : 1);
}
__device__ __forceinline__ int mask_padded(const void* mask, int mode, int idx) {
    if (mode == 0) return ((const unsigned char*)mask)[idx] != 0;
    if (mode == 1) return ((const int*)mask)[idx] != 0;
    return ((const float*)mask)[idx] != 0.0f;
}

// ---------------- LN core ----------
__device__ __forceinline__ float4 ln_row(const float* __restrict__ in,
                                         const float* __restrict__ gamma,
                                         const float* __restrict__ beta, int row, int t) {
    float4 v = reinterpret_cast<const float4*>(in + (size_t)row * DD)[t];
    float s  = (v.x + v.y) + (v.z + v.w);
    float ss = v.x * v.x + v.y * v.y + v.z * v.z + v.w * v.w;
    __shared__ float red[16];
    __shared__ float s_mu, s_rstd;
#pragma unroll
    for (int o = 16; o; o >>= 1) {
        s  += __shfl_xor_sync(0xffffffffu, s, o);
        ss += __shfl_xor_sync(0xffffffffu, ss, o);
    }
    if ((t & 31) == 0) { red[t >> 5] = s; red[(t >> 5) + 8] = ss; }
    __syncthreads();
    if (t < 8) {
        float a = red[t], b2 = red[t + 8];
#pragma unroll
        for (int o = 4; o; o >>= 1) {
            a  += __shfl_xor_sync(0xffu, a, o);
            b2 += __shfl_xor_sync(0xffu, b2, o);
        }
        if (t == 0) {
            float mu = a * (1.0f / DD);
            float var = b2 * (1.0f / DD) - mu * mu;
            s_mu = mu; s_rstd = rsqrtf(var + 1e-5f);
        }
    }
    __syncthreads();
    const float mu = s_mu, rstd = s_rstd;
    float4 g4 = reinterpret_cast<const float4*>(gamma)[t];
    float4 b4 = reinterpret_cast<const float4*>(beta)[t];
    float4 o4;
    o4.x = (v.x - mu) * rstd * g4.x + b4.x;
    o4.y = (v.y - mu) * rstd * g4.y + b4.y;
    o4.z = (v.z - mu) * rstd * g4.z + b4.z;
    o4.w = (v.w - mu) * rstd * g4.w + b4.w;
    return o4;
}

__device__ __forceinline__ void write_hilo_to(__nv_bfloat16* hp, __nv_bfloat16* lp,
                                              size_t elem, float a, float b, float c, float d) {
    float hf0 = __bfloat162float(__float2bfloat16(a));
    float hf1 = __bfloat162float(__float2bfloat16(b));
    float hf2 = __bfloat162float(__float2bfloat16(c));
    float hf3 = __bfloat162float(__float2bfloat16(d));
    uint2 hw = make_uint2(pack_bf2(hf0, hf1), pack_bf2(hf2, hf3));
    uint2 lw = make_uint2(pack_bf2(a - hf0, b - hf1), pack_bf2(c - hf2, d - hf3));
    *reinterpret_cast<uint2*>(hp + elem) = hw;
    *reinterpret_cast<uint2*>(lp + elem) = lw;
}

// LN for x: bf16 hi/lo into KV-row layout
__global__ void __launch_bounds__(256) ln_x_kernel(const float* __restrict__ in,
                                                   const float* __restrict__ gamma,
                                                   const float* __restrict__ beta) {
    const int row = blockIdx.x;
    const int t = threadIdx.x;
    float4 o4 = ln_row(in, gamma, beta, row, t);
    const int b = row / FF, s = row - b * FF;
    const size_t kvrow = (size_t)b * KVLEN + s;
    write_hilo_to(g_ahi, g_alo, kvrow * DD + t * 4, o4.x, o4.y, o4.z, o4.w);
}

// LN for latents: ungated hi/lo (q GEMM A) + gated hi/lo KV rows
__global__ void __launch_bounds__(256) ln_lat_kernel(const float* __restrict__ in,
                                                     const float* __restrict__ gamma,
                                                     const float* __restrict__ beta,
                                                     const float* __restrict__ gate_p) {
    const int row = blockIdx.x;               // 0 .. BB*NL-1
    const int t = threadIdx.x;
    float4 o4 = ln_row(in, gamma, beta, row, t);
    write_hilo_to(g_lathi, g_latlo, (size_t)row * DD + t * 4, o4.x, o4.y, o4.z, o4.w);
    const float g = *gate_p;
    const int b = row / NL, l = row - b * NL;
    const size_t kvrow = (size_t)b * KVLEN + FF + l;
    write_hilo_to(g_ahi, g_alo, kvrow * DD + t * 4, o4.x * g, o4.y * g, o4.z * g, o4.w * g);
}

// ---------------- W transpose + bf16 split: [Kdim][Ndim] fp32 -> [Ndim][Kdim] hi/lo ------
__global__ void __launch_bounds__(256) wtrans_kernel(const float* __restrict__ W,
                                                     __nv_bfloat16* __restrict__ dhi,
                                                     __nv_bfloat16* __restrict__ dlo,
                                                     int Kdim, int Ndim) {
    __shared__ float tbuf[32][33];
    const int k0 = blockIdx.x * 32, n0 = blockIdx.y * 32;
    const int tx = threadIdx.x & 31, ty = threadIdx.x >> 5;   // 32 x 8
#pragma unroll
    for (int i = 0; i < 4; i++)
        tbuf[ty + 8 * i][tx] = W[(size_t)(k0 + ty + 8 * i) * Ndim + n0 + tx];
    __syncthreads();
#pragma unroll
    for (int i = 0; i < 4; i++) {
        const int n = n0 + ty + 8 * i, k = k0 + tx;
        float v = tbuf[tx][ty + 8 * i];
        __nv_bfloat16 hi = __float2bfloat16(v);
        float lo = v - __bfloat162float(hi);
        const size_t idx = (size_t)n * Kdim + k;
        dhi[idx] = hi;
        dlo[idx] = __float2bfloat16(lo);
    }
}

// ================= generic bf16-split MMA GEMM =================
// C = alpha * A[M x K] @ B[N x K]^T  (3-term split, fp32 acc)
// mode 0: fp32 C.  mode 1: bf16 hi/lo pair (Chi/Clo).
// Tile 128x128, BK=32, 2-stage cp.async (80KB smem -> 2 CTAs/SM), 8 warps (2m x 4n).
#define BKK    32
#define APAD   40                    // 80B row stride: conflict-free ldmatrix
#define KVTILE (128 * APAD)          // bf16 elems per array per stage
#define MMA_SMEM (8 * KVTILE * 2)    // 2 stages x 4 arrays = 81920 B

__device__ __forceinline__ void issue_tiles(uint32_t sbase, int buf,
                                            const __nv_bfloat16* __restrict__ Ah,
                                            const __nv_bfloat16* __restrict__ Al,
                                            const __nv_bfloat16* __restrict__ Bh,
                                            const __nv_bfloat16* __restrict__ Bl,
                                            int m0, int n0, int k0, int strideK, int tid) {
#pragma unroll
    for (int arr = 0; arr < 4; arr++) {
        const __nv_bfloat16* src = (arr == 0) ? Ah : (arr == 1) ? Al : (arr == 2) ? Bh : Bl;
        const int rbase = (arr < 2) ? m0 : n0;
#pragma unroll
        for (int i = 0; i < 2; i++) {
            int id = tid + 256 * i;                 // 0..511
            int row = id >> 2, c4 = id & 3;
            const __nv_bfloat16* gp = src + (size_t)(rbase + row) * strideK + k0 + c4 * 8;
            uint32_t sp = sbase + ((buf * 4 + arr) * KVTILE + row * APAD + c4 * 8) * 2;
            cp16(sp, gp);
        }
    }
}

__device__ __forceinline__ void compute_chunk(uint32_t sbase, int buf,
                                              int warp_m, int warp_n, int lane,
                                              float (&acc)[4][4][4]) {
    const uint32_t ab = sbase + ((buf * 4 + 0) * KVTILE) * 2;
    const uint32_t lb = sbase + ((buf * 4 + 1) * KVTILE) * 2;
    const uint32_t bb = sbase + ((buf * 4 + 2) * KVTILE) * 2;
    const uint32_t vb = sbase + ((buf * 4 + 3) * KVTILE) * 2;
#pragma unroll
    for (int ks = 0; ks < 2; ks++) {
        const int koff = ks * 16;
        uint32_t ah[4][4], al[4][4];
#pragma unroll
        for (int mt = 0; mt < 4; mt++) {
            const uint32_t ro = ((warp_m * 64 + mt * 16 + (lane & 15)) * APAD
                                 + koff + (lane >> 4) * 8) * 2;
            ldsm_x4(ah[mt], ab + ro);
            ldsm_x4(al[mt], lb + ro);
        }
        uint32_t bh[4][2], bl[4][2];
#pragma unroll
        for (int p = 0; p < 2; p++) {
            const int g2 = lane >> 3;               // 0..3
            const uint32_t ro = ((warp_n * 32 + p * 16 + (g2 >> 1) * 8 + (lane & 7)) * APAD
                                 + koff + (g2 & 1) * 8) * 2;
            uint32_t r[4];
            ldsm_x4(r, bb + ro);
            bh[2 * p][0] = r[0]; bh[2 * p][1] = r[1];
            bh[2 * p + 1][0] = r[2]; bh[2 * p + 1][1] = r[3];
            ldsm_x4(r, vb + ro);
            bl[2 * p][0] = r[0]; bl[2 * p][1] = r[1];
            bl[2 * p + 1][0] = r[2]; bl[2 * p + 1][1] = r[3];
        }
        // term-major ordering: same-acc RAW 16 MMAs apart
#pragma unroll
        for (int mt = 0; mt < 4; mt++)
#pragma unroll
            for (int nt = 0; nt < 4; nt++) mma_bf16(acc[mt][nt], ah[mt], bh[nt]);
#pragma unroll
        for (int mt = 0; mt < 4; mt++)
#pragma unroll
            for (int nt = 0; nt < 4; nt++) mma_bf16(acc[mt][nt], ah[mt], bl[nt]);
#pragma unroll
        for (int mt = 0; mt < 4; mt++)
#pragma unroll
            for (int nt = 0; nt < 4; nt++) mma_bf16(acc[mt][nt], al[mt], bh[nt]);
    }
}

__global__ void __launch_bounds__(256, 2) mma_gemm_kernel(
    const __nv_bfloat16* __restrict__ Ah, const __nv_bfloat16* __restrict__ Al,
    const __nv_bfloat16* __restrict__ Bh, const __nv_bfloat16* __restrict__ Bl,
    float* __restrict__ C, __nv_bfloat16* __restrict__ Chi, __nv_bfloat16* __restrict__ Clo,
    int K, int ldc, float alpha, int mode) {
    extern __shared__ __nv_bfloat16 sm[];
    const uint32_t sbase = smem_to_u32(sm);
    const int tid = threadIdx.x;
    const int lane = tid & 31, wid = tid >> 5;
    const int warp_m = wid >> 2, warp_n = wid & 3;
    const int m0 = blockIdx.y * 128, n0 = blockIdx.x * 128;

    float acc[4][4][4];
#pragma unroll
    for (int i = 0; i < 4; i++)
#pragma unroll
        for (int j = 0; j < 4; j++)
#pragma unroll
            for (int q = 0; q < 4; q++) acc[i][j][q] = 0.f;

    const int NITER = K / BKK;
    issue_tiles(sbase, 0, Ah, Al, Bh, Bl, m0, n0, 0, K, tid);
    CP_COMMIT();

    for (int c = 0; c < NITER; c++) {
        const int buf = c & 1;
        if (c < NITER - 1) {
            issue_tiles(sbase, buf ^ 1, Ah, Al, Bh, Bl, m0, n0, (c + 1) * BKK, K, tid);
            CP_COMMIT();
            CP_WAIT1();
        } else {
            CP_WAIT0();
        }
        __syncthreads();
        compute_chunk(sbase, buf, warp_m, warp_n, lane, acc);
        __syncthreads();
    }

#pragma unroll
    for (int mt = 0; mt < 4; mt++) {
        const int r0 = m0 + warp_m * 64 + mt * 16 + (lane >> 2);
#pragma unroll
        for (int nt = 0; nt < 4; nt++) {
            const int cc = n0 + warp_n * 32 + nt * 8 + (lane & 3) * 2;
            float s0 = acc[mt][nt][0] * alpha, s1 = acc[mt][nt][1] * alpha;
            float s2 = acc[mt][nt][2] * alpha, s3 = acc[mt][nt][3] * alpha;
            if (mode == 0) {
                *reinterpret_cast<float2*>(&C[(size_t)r0 * ldc + cc]) = make_float2(s0, s1);
                *reinterpret_cast<float2*>(&C[(size_t)(r0 + 8) * ldc + cc]) = make_float2(s2, s3);
            } else {
                uint32_t hp0 = pack_bf2(s0, s1), hp1 = pack_bf2(s2, s3);
                __nv_bfloat162 h0 = *reinterpret_cast<__nv_bfloat162*>(&hp0);
                __nv_bfloat162 h1 = *reinterpret_cast<__nv_bfloat162*>(&hp1);
                uint32_t lp0 = pack_bf2(s0 - __bfloat162float(h0.x), s1 - __bfloat162float(h0.y));
                uint32_t lp1 = pack_bf2(s2 - __bfloat162float(h1.x), s3 - __bfloat162float(h1.y));
                *reinterpret_cast<uint32_t*>(&Chi[(size_t)r0 * ldc + cc]) = hp0;
                *reinterpret_cast<uint32_t*>(&Clo[(size_t)r0 * ldc + cc]) = lp0;
                *reinterpret_cast<uint32_t*>(&Chi[(size_t)(r0 + 8) * ldc + cc]) = hp1;
                *reinterpret_cast<uint32_t*>(&Clo[(size_t)(r0 + 8) * ldc + cc]) = lp1;
            }
        }
    }
}

// ---------------- sim on tensor cores: S = q @ K^T per bh, fused mask ----------------
// grid (65, 64). CTA: 64 q x 128 kv, contraction K=64 head dims, 3-term bf16 split.
#define SPAD   72                    // 144B row stride: conflict-free ldmatrix
#define OQH    0
#define OQL    (64 * SPAD)
#define OKH    (2 * 64 * SPAD)
#define OKL    (2 * 64 * SPAD + 128 * SPAD)
#define SIM_SMEM ((2 * 64 * SPAD + 2 * 128 * SPAD) * 2)   // 55296 B

__global__ void __launch_bounds__(256, 2) sim_mma_kernel(const void* __restrict__ mask) {
    extern __shared__ __nv_bfloat16 sm[];
    const uint32_t sb = smem_to_u32(sm);
    const int tid = threadIdx.x, lane = tid & 31, wid = tid >> 5;
    const int warp_m = wid >> 2, warp_n = wid & 3;
    const int bh = blockIdx.y, b = bh >> 3, h = bh & 7;
    const int kv0 = blockIdx.x * 128;

    // Q tiles: 64 rows x 64 dims, hi+lo  (1024 cp16)
#pragma unroll
    for (int i = 0; i < 4; i++) {
        int id = tid + 256 * i;
        int arr = id >> 9, rem = id & 511, row = rem >> 3, c = rem & 7;
        const __nv_bfloat16* src = (arr ? g_qlo : g_qhi)
            + (size_t)(b * NL + row) * INNERD + h * DHD + c * 8;
        cp16(sb + ((arr ? OQL : OQH) + row * SPAD + c * 8) * 2, src);
    }
    // K tiles: 128 kv rows x 64 dims, hi+lo  (2048 cp16, zero-fill OOB rows)
#pragma unroll
    for (int i = 0; i < 8; i++) {
        int id = tid + 256 * i;
        int arr = id >> 10, rem = id & 1023, row = rem >> 3, c = rem & 7;
        int kvr = kv0 + row;
        int pred = kvr < KVLEN;
        const __nv_bfloat16* src = (arr ? g_klo : g_khi)
            + ((size_t)b * KVLEN + (pred ? kvr : 0)) * INNERD + h * DHD + c * 8;
        cp16z(sb + ((arr ? OKL : OKH) + row * SPAD + c * 8) * 2, src, pred);
    }
    CP_COMMIT();
    CP_WAIT0();
    __syncthreads();

    float acc[2][4][4];
#pragma unroll
    for (int i = 0; i < 2; i++)
#pragma unroll
        for (int j = 0; j < 4; j++)
#pragma unroll
            for (int q = 0; q < 4; q++) acc[i][j][q] = 0.f;

#pragma unroll
    for (int ks = 0; ks < 4; ks++) {
        const int koff = ks * 16;
        uint32_t ah[2][4], al[2][4];
#pragma unroll
        for (int mt = 0; mt < 2; mt++) {
            const uint32_t ro = ((warp_m * 32 + mt * 16 + (lane & 15)) * SPAD
                                 + koff + (lane >> 4) * 8) * 2;
            ldsm_x4(ah[mt], sb + OQH * 2 + ro);
            ldsm_x4(al[mt], sb + OQL * 2 + ro);
        }
        uint32_t bh_[4][2], bl_[4][2];
#pragma unroll
        for (int p = 0; p < 2; p++) {
            const int g2 = lane >> 3;
            const uint32_t ro = ((warp_n * 32 + p * 16 + (g2 >> 1) * 8 + (lane & 7)) * SPAD
                                 + koff + (g2 & 1) * 8) * 2;
            uint32_t r[4];
            ldsm_x4(r, sb + OKH * 2 + ro);
            bh_[2 * p][0] = r[0]; bh_[2 * p][1] = r[1];
            bh_[2 * p + 1][0] = r[2]; bh_[2 * p + 1][1] = r[3];
            ldsm_x4(r, sb + OKL * 2 + ro);
            bl_[2 * p][0] = r[0]; bl_[2 * p][1] = r[1];
            bl_[2 * p + 1][0] = r[2]; bl_[2 * p + 1][1] = r[3];
        }
#pragma unroll
        for (int mt = 0; mt < 2; mt++)
#pragma unroll
            for (int nt = 0; nt < 4; nt++) mma_bf16(acc[mt][nt], ah[mt], bh_[nt]);
#pragma unroll
        for (int mt = 0; mt < 2; mt++)
#pragma unroll
            for (int nt = 0; nt < 4; nt++) mma_bf16(acc[mt][nt], ah[mt], bl_[nt]);
#pragma unroll
        for (int mt = 0; mt < 2; mt++)
#pragma unroll
            for (int nt = 0; nt < 4; nt++) mma_bf16(acc[mt][nt], al[mt], bh_[nt]);
    }

    // epilogue: mask + store logits
    const int mode = g_mask_mode;
#pragma unroll
    for (int mt = 0; mt < 2; mt++) {
        const int r = warp_m * 32 + mt * 16 + (lane >> 2);
        float* d0 = g_sim + ((size_t)bh * NL + r) * KVLEN;
        float* d1 = g_sim + ((size_t)bh * NL + r + 8) * KVLEN;
#pragma unroll
        for (int nt = 0; nt < 4; nt++) {
            const int cc = kv0 + warp_n * 32 + nt * 8 + (lane & 3) * 2;
            if (cc < KVLEN) {
                int i0 = (cc < FF) && mask_padded(mask, mode, b * FF + cc);
                int i1 = (cc + 1 < FF) && mask_padded(mask, mode, b * FF + cc + 1);
                *reinterpret_cast<float2*>(d0 + cc) =
                    make_float2(i0 ? NEGINF : acc[mt][nt][0], i1 ? NEGINF : acc[mt][nt][1]);
                *reinterpret_cast<float2*>(d1 + cc) =
                    make_float2(i0 ? NEGINF : acc[mt][nt][2], i1 ? NEGINF : acc[mt][nt][3]);
            }
        }
    }
}

// ---------------- rowstat: per-row max + 1/sumexp ----------------
__global__ void __launch_bounds__(256) rowstat_kernel() {
    const int row = blockIdx.x;
    const int t = threadIdx.x;
    const float4* p = reinterpret_cast<const float4*>(g_sim + (size_t)row * KVLEN);
    const int NV = KVLEN / 4;   // 2064
    __shared__ float red[8];
    __shared__ float s_max, s_sum;

    float m = -3.4e38f;
    for (int idx = t; idx < NV; idx += 256) {
        float4 v = p[idx];
        m = fmaxf(m, fmaxf(fmaxf(v.x, v.y), fmaxf(v.z, v.w)));
    }
#pragma unroll
    for (int o = 16; o; o >>= 1) m = fmaxf(m, __shfl_xor_sync(0xffffffffu, m, o));
    if ((t & 31) == 0) red[t >> 5] = m;
    __syncthreads();
    if (t < 8) {
        float a = red[t];
#pragma unroll
        for (int o = 4; o; o >>= 1) a = fmaxf(a, __shfl_xor_sync(0xffu, a, o));
        if (t == 0) s_max = a;
    }
    __syncthreads();
    m = s_max;
    float s = 0.f;
    for (int idx = t; idx < NV; idx += 256) {
        float4 v = p[idx];
        s += fast_exp(v.x - m) + fast_exp(v.y - m) + fast_exp(v.z - m) + fast_exp(v.w - m);
    }
#pragma unroll
    for (int o = 16; o; o >>= 1) s += __shfl_xor_sync(0xffffffffu, s, o);
    __syncthreads();
    if ((t & 31) == 0) red[t >> 5] = s;
    __syncthreads();
    if (t < 8) {
        float a = red[t];
#pragma unroll
        for (int o = 4; o; o >>= 1) a += __shfl_xor_sync(0xffu, a, o);
        if (t == 0) s_sum = a;
    }
    __syncthreads();
    if (t == 0) { g_rowm[row] = m; g_rowrl[row] = 1.0f / s_sum; }
}

// ---------------- attn @ v with in-loop softmax normalization, split-K partials ----------
__global__ void __launch_bounds__(256) pv_kernel() {
    const int split = blockIdx.x, bh = blockIdx.y;
    const int b = bh >> 3, h = bh & 7;
    const int kvs = split * CHUNK;
    const int kve = min(kvs + CHUNK, KVLEN);
    __shared__ float Ps[16][68];
    __shared__ float Vs[16][68];
    const int t = threadIdx.x;
    const int tx = t & 15, ty = t >> 4;
    const int prow = t >> 2, pk = (t & 3) * 4;
    const int vrow = t >> 4, vd = (t & 15) * 4;
    float acc[4][4];
#pragma unroll
    for (int i = 0; i < 4; i++)
#pragma unroll
        for (int j = 0; j < 4; j++) acc[i][j] = 0.f;

    const float* pbase = g_sim + (size_t)bh * NL * KVLEN;
    const float* vbase = g_v + (size_t)b * KVLEN * INNERD + h * DHD;
    const float rm = g_rowm[bh * NL + prow];
    const float rl = g_rowrl[bh * NL + prow];

    for (int k0 = kvs; k0 < kve; k0 += 16) {
        float4 a4 = *reinterpret_cast<const float4*>(pbase + (size_t)prow * KVLEN + k0 + pk);
        Ps[pk + 0][prow] = fast_exp(a4.x - rm) * rl;
        Ps[pk + 1][prow] = fast_exp(a4.y - rm) * rl;
        Ps[pk + 2][prow] = fast_exp(a4.z - rm) * rl;
        Ps[pk + 3][prow] = fast_exp(a4.w - rm) * rl;
        *reinterpret_cast<float4*>(&Vs[vrow][vd]) =
            *reinterpret_cast<const float4*>(vbase + (size_t)(k0 + vrow) * INNERD + vd);
        __syncthreads();
#pragma unroll
        for (int k = 0; k < 16; k++) {
            float pf[4], vf[4];
            *reinterpret_cast<float4*>(&pf[0]) = *reinterpret_cast<const float4*>(&Ps[k][ty * 4]);
            *reinterpret_cast<float4*>(&vf[0]) = *reinterpret_cast<const float4*>(&Vs[k][tx * 4]);
#pragma unroll
            for (int i = 0; i < 4; i++)
#pragma unroll
                for (int j = 0; j < 4; j++) acc[i][j] += pf[i] * vf[j];
        }
        __syncthreads();
    }

    float* obase = g_opart + (size_t)split * (BB * NL * INNERD)
                 + (size_t)(b * NL) * INNERD + h * DHD;
#pragma unroll
    for (int i = 0; i < 4; i++)
        *reinterpret_cast<float4*>(&obase[(size_t)(ty * 4 + i) * INNERD + tx * 4]) =
            make_float4(acc[i][0], acc[i][1], acc[i][2], acc[i][3]);
}

// ---------------- split-K reduction -> bf16 hi/lo operand for out GEMM ----------------
__global__ void __launch_bounds__(256) reduce_kernel() {
    const int i = blockIdx.x * blockDim.x + threadIdx.x;
    float s = 0.f;
#pragma unroll
    for (int k = 0; k < NSPLIT; k++) s += g_opart[(size_t)k * (BB * NL * INNERD) + i];
    __nv_bfloat16 hi = __float2bfloat16(s);
    g_ohi[i] = hi;
    g_olo[i] = __float2bfloat16(s - __bfloat162float(hi));
}

// ---------------- launch ----------------
extern "C" void kernel_launch(void* const* d_in, const int* in_sizes, int n_in,
                              void* d_out, int out_size) {
    const float* x    = (const float*)d_in[0];
    const float* lat  = (const float*)d_in[1];
    const void*  mask = d_in[2];
    const float* gate = (const float*)d_in[3];
    const float* gm   = (const float*)d_in[4];
    const float* bm   = (const float*)d_in[5];
    const float* gl   = (const float*)d_in[6];
    const float* bl   = (const float*)d_in[7];
    const float* Wq   = (const float*)d_in[8];
    const float* Wk   = (const float*)d_in[9];
    const float* Wv   = (const float*)d_in[10];
    const float* Wout = (const float*)d_in[11];
    float* out = (float*)d_out;

    __nv_bfloat16 *p_ahi, *p_alo, *p_bhi, *p_blo, *p_lathi, *p_latlo;
    __nv_bfloat16 *p_wqhi, *p_wqlo, *p_wohi, *p_wolo, *p_ohi, *p_olo;
    __nv_bfloat16 *p_qhi, *p_qlo, *p_khi, *p_klo;
    float *p_v;
    cudaGetSymbolAddress((void**)&p_ahi,   g_ahi);
    cudaGetSymbolAddress((void**)&p_alo,   g_alo);
    cudaGetSymbolAddress((void**)&p_bhi,   g_bhi);
    cudaGetSymbolAddress((void**)&p_blo,   g_blo);
    cudaGetSymbolAddress((void**)&p_lathi, g_lathi);
    cudaGetSymbolAddress((void**)&p_latlo, g_latlo);
    cudaGetSymbolAddress((void**)&p_wqhi,  g_wqhi);
    cudaGetSymbolAddress((void**)&p_wqlo,  g_wqlo);
    cudaGetSymbolAddress((void**)&p_wohi,  g_wohi);
    cudaGetSymbolAddress((void**)&p_wolo,  g_wolo);
    cudaGetSymbolAddress((void**)&p_ohi,   g_ohi);
    cudaGetSymbolAddress((void**)&p_olo,   g_olo);
    cudaGetSymbolAddress((void**)&p_qhi,   g_qhi);
    cudaGetSymbolAddress((void**)&p_qlo,   g_qlo);
    cudaGetSymbolAddress((void**)&p_khi,   g_khi);
    cudaGetSymbolAddress((void**)&p_klo,   g_klo);
    cudaGetSymbolAddress((void**)&p_v,     g_v);

    cudaFuncSetAttribute(mma_gemm_kernel, cudaFuncAttributeMaxDynamicSharedMemorySize, MMA_SMEM);
    cudaFuncSetAttribute(sim_mma_kernel,  cudaFuncAttributeMaxDynamicSharedMemorySize, SIM_SMEM);

    detect_mask_kernel<<<1, 256>>>((const unsigned int*)mask);
    ln_x_kernel<<<BB * FF, 256>>>(x, gm, bm);
    ln_lat_kernel<<<BB * NL, 256>>>(lat, gl, bl, gate);
    wtrans_kernel<<<dim3(DD / 32, INNERD / 32), 256>>>(Wk, p_bhi, p_blo, DD, INNERD);
    wtrans_kernel<<<dim3(DD / 32, INNERD / 32), 256>>>(Wv, p_bhi + INNERD * DD,
                                                       p_blo + INNERD * DD, DD, INNERD);
    wtrans_kernel<<<dim3(DD / 32, INNERD / 32), 256>>>(Wq, p_wqhi, p_wqlo, DD, INNERD);
    wtrans_kernel<<<dim3(INNERD / 32, DD / 32), 256>>>(Wout, p_wohi, p_wolo, INNERD, DD);
    // q = LN(lat) @ Wq * SCALE -> bf16 hi/lo
    mma_gemm_kernel<<<dim3(INNERD / 128, (BB * NL) / 128), 256, MMA_SMEM>>>(
        p_lathi, p_latlo, p_wqhi, p_wqlo, nullptr, p_qhi, p_qlo, DD, INNERD, QSCALE, 1);
    // K -> bf16 hi/lo
    mma_gemm_kernel<<<dim3(INNERD / 128, MROWS / 128), 256, MMA_SMEM>>>(
        p_ahi, p_alo, p_bhi, p_blo, nullptr, p_khi, p_klo, DD, INNERD, 1.0f, 1);
    // V -> fp32
    mma_gemm_kernel<<<dim3(INNERD / 128, MROWS / 128), 256, MMA_SMEM>>>(
        p_ahi, p_alo, p_bhi + INNERD * DD, p_blo + INNERD * DD, p_v, nullptr, nullptr,
        DD, INNERD, 1.0f, 0);
    // attention: tensor-core logits -> row stats -> normalized pv
    sim_mma_kernel<<<dim3((KVLEN + 127) / 128, BB * HH), 256, SIM_SMEM>>>(mask);
    rowstat_kernel<<<BB * HH * NL, 256>>>();
    pv_kernel<<<dim3(NSPLIT, BB * HH), 256>>>();
    reduce_kernel<<<(BB * NL * INNERD) / 256, 256>>>();
    // out = o @ Wout -> fp32
    mma_gemm_kernel<<<dim3(DD / 128, (BB * NL) / 128), 256, MMA_SMEM>>>(
        p_ohi, p_olo, p_wohi, p_wolo, out, nullptr, nullptr, INNERD, DD, 1.0f, 0);
}